// round 12
// baseline (speedup 1.0000x reference)
#include <cuda_runtime.h>
#include <cuda_bf16.h>
#include <math.h>
#include <stdint.h>

#define N_NODES 20000
#define N_EDGES 320000
#define N_REL   100
#define F_DIM   256
#define FF_DIM  1024
#define H_HEADS 8
#define D_HEAD  32
#define SLOPE   0.2f
#define MAXD    128
#define PSTRIDE 768   // fused projection row stride [fh | ftl | fen]

// ======================= scratch (static device globals) =======================
__device__ __align__(16) float g_proj[N_NODES * PSTRIDE];   // [fh|ftl|fen]
__device__ __align__(16) float g_fr[N_REL * F_DIM];
__device__ int   g_deg[N_NODES];
__device__ int   g_cursor[N_NODES];
__device__ int   g_rowptr[N_NODES + 1];
__device__ float g_logdeg[N_NODES];
__device__ int   g_csr_src[N_EDGES];
__device__ int   g_csr_rid[N_EDGES];
__device__ __align__(16) float g_a[N_EDGES * H_HEADS];
__device__ __align__(16) float g_feat[N_NODES * F_DIM];
__device__ __align__(16) float g_feat2[N_NODES * F_DIM];
__device__ __align__(16) float g_rst[N_NODES * F_DIM];

// bf16 split activations
__device__ __align__(16) __nv_bfloat16 g_xh[N_NODES * F_DIM];
__device__ __align__(16) __nv_bfloat16 g_xl[N_NODES * F_DIM];
__device__ __align__(16) __nv_bfloat16 g_rh[N_REL * F_DIM];
__device__ __align__(16) __nv_bfloat16 g_rl[N_REL * F_DIM];
__device__ __align__(16) __nv_bfloat16 g_yh[N_NODES * F_DIM];
__device__ __align__(16) __nv_bfloat16 g_yl[N_NODES * F_DIM];
__device__ __align__(16) __nv_bfloat16 g_hidh[N_NODES * FF_DIM];
__device__ __align__(16) __nv_bfloat16 g_hidl[N_NODES * FF_DIM];

// bf16 split + transposed weights [N,K] K-major
__device__ __align__(16) __nv_bfloat16 g_Wph[3 * F_DIM * F_DIM], g_Wpl[3 * F_DIM * F_DIM]; // fused proj
__device__ __align__(16) __nv_bfloat16 g_Wrh[F_DIM * F_DIM], g_Wrl[F_DIM * F_DIM];
__device__ __align__(16) __nv_bfloat16 g_W1h[FF_DIM * F_DIM], g_W1l[FF_DIM * F_DIM];
__device__ __align__(16) __nv_bfloat16 g_W2h[F_DIM * FF_DIM], g_W2l[F_DIM * FF_DIM];

// ======================= CSR build =======================
__global__ void zero_counts_kernel() {
    int i = blockIdx.x * 256 + threadIdx.x;
    if (i < N_NODES) { g_deg[i] = 0; g_cursor[i] = 0; }
}
__global__ void count_kernel(const int* __restrict__ dst) {
    int e = blockIdx.x * 256 + threadIdx.x;
    if (e < N_EDGES) atomicAdd(&g_deg[dst[e]], 1);
}
__global__ void scan_kernel() {
    __shared__ int sh[1024];
    __shared__ int carry_s;
    int t = threadIdx.x;
    if (t == 0) carry_s = 0;
    __syncthreads();
    for (int base = 0; base < N_NODES; base += 1024) {
        int i = base + t;
        int v = (i < N_NODES) ? g_deg[i] : 0;
        sh[t] = v;
        __syncthreads();
        for (int o = 1; o < 1024; o <<= 1) {
            int tmp = (t >= o) ? sh[t - o] : 0;
            __syncthreads();
            sh[t] += tmp;
            __syncthreads();
        }
        int incl = sh[t];
        if (i < N_NODES) {
            g_rowptr[i] = carry_s + incl - v;
            g_logdeg[i] = logf((float)v) * (1.0f / (float)D_HEAD);
        }
        __syncthreads();
        if (t == 1023) carry_s += incl;
        __syncthreads();
    }
    if (t == 0) g_rowptr[N_NODES] = N_EDGES;
}
__global__ void scatter_kernel(const int* __restrict__ src, const int* __restrict__ dst,
                               const int* __restrict__ rid) {
    int e = blockIdx.x * 256 + threadIdx.x;
    if (e < N_EDGES) {
        int d = dst[e];
        int p = g_rowptr[d] + atomicAdd(&g_cursor[d], 1);
        g_csr_src[p] = src[e];
        g_csr_rid[p] = rid[e];
    }
}

// ======================= LayerNorm -> bf16 hi/lo split =======================
__global__ void ln_split_kernel(const float* __restrict__ in, const float* __restrict__ gg,
                                const float* __restrict__ bb,
                                __nv_bfloat16* __restrict__ oh, __nv_bfloat16* __restrict__ ol) {
    int row = blockIdx.x;
    int t = threadIdx.x;
    const float* x = in + (size_t)row * F_DIM;
    float v = x[t];
    float s = v, s2 = v * v;
#pragma unroll
    for (int o = 16; o; o >>= 1) {
        s  += __shfl_xor_sync(0xFFFFFFFFu, s, o);
        s2 += __shfl_xor_sync(0xFFFFFFFFu, s2, o);
    }
    __shared__ float sh[8], sh2[8];
    int w = t >> 5, l = t & 31;
    if (l == 0) { sh[w] = s; sh2[w] = s2; }
    __syncthreads();
    if (w == 0) {
        float a = (l < 8) ? sh[l] : 0.f;
        float a2 = (l < 8) ? sh2[l] : 0.f;
#pragma unroll
        for (int o = 4; o; o >>= 1) {
            a  += __shfl_xor_sync(0xFFFFFFFFu, a, o);
            a2 += __shfl_xor_sync(0xFFFFFFFFu, a2, o);
        }
        if (l == 0) { sh[0] = a; sh2[0] = a2; }
    }
    __syncthreads();
    float mean = sh[0] * (1.0f / F_DIM);
    float var = sh2[0] * (1.0f / F_DIM) - mean * mean;
    float inv = rsqrtf(var + 1e-5f);
    float r = (v - mean) * inv * gg[t] + bb[t];
    __nv_bfloat16 h = __float2bfloat16(r);
    size_t idx = (size_t)row * F_DIM + t;
    oh[idx] = h;
    ol[idx] = __float2bfloat16(r - __bfloat162float(h));
}

// ======================= weight transpose + split: W[K,N] -> Wt[N,K] bf16 hi/lo =======================
__global__ void trans_split_kernel(const float* __restrict__ W, int K, int Nc,
                                   __nv_bfloat16* __restrict__ Th, __nv_bfloat16* __restrict__ Tl) {
    __shared__ float t[32][33];
    int n0 = blockIdx.x * 32, k0 = blockIdx.y * 32;
    int tx = threadIdx.x, ty = threadIdx.y;  // 32 x 8
#pragma unroll
    for (int j = 0; j < 32; j += 8)
        t[ty + j][tx] = W[(size_t)(k0 + ty + j) * Nc + n0 + tx];
    __syncthreads();
#pragma unroll
    for (int j = 0; j < 32; j += 8) {
        float v = t[tx][ty + j];
        int n = n0 + ty + j, k = k0 + tx;
        __nv_bfloat16 h = __float2bfloat16(v);
        Th[(size_t)n * K + k] = h;
        Tl[(size_t)n * K + k] = __float2bfloat16(v - __bfloat162float(h));
    }
}

// ======================= HMMA GEMM (cp.async double-buffered, 128x256 tile) =======================
// C[M,Nc] = A[M,K] @ Wt[Nc,K]^T, mma.sync m16n8k16 bf16, 3-term split (fp32 accum).
// CTA: 256 thr / 8 warps (2x4), warp tile 64x64, K-chunk 32, 2-stage pipeline.
// mode 0: C=fp32. mode 1: +bias, relu -> Ch/Cl bf16 split. mode 2: +bias+resid -> fp32.

#define KC 32
#define LDT 40                       // smem row stride in bf16 (KC + 8 pad)
#define TSZ_A (128 * LDT)            // A tile elems
#define TSZ_B (256 * LDT)            // B tile elems
#define STG (2 * TSZ_A + 2 * TSZ_B)  // elems per stage
#define GEMM_SMEM (2 * STG * 2)      // bytes, 2 stages

__device__ __forceinline__ void mma16816(float* c, uint32_t a0, uint32_t a1, uint32_t a2,
                                         uint32_t a3, uint32_t b0, uint32_t b1) {
    asm volatile(
        "mma.sync.aligned.m16n8k16.row.col.f32.bf16.bf16.f32 "
        "{%0,%1,%2,%3}, {%4,%5,%6,%7}, {%8,%9}, {%0,%1,%2,%3};"
        : "+f"(c[0]), "+f"(c[1]), "+f"(c[2]), "+f"(c[3])
        : "r"(a0), "r"(a1), "r"(a2), "r"(a3), "r"(b0), "r"(b1));
}

__device__ __forceinline__ void cp_async16(uint32_t saddr, const void* gptr) {
    asm volatile("cp.async.cg.shared.global [%0], [%1], 16;" :: "r"(saddr), "l"(gptr));
}
#define CP_COMMIT() asm volatile("cp.async.commit_group;" ::: "memory")
#define CP_WAIT0()  asm volatile("cp.async.wait_group 0;" ::: "memory")
#define CP_WAIT1()  asm volatile("cp.async.wait_group 1;" ::: "memory")

__global__ void __launch_bounds__(256, 1) gemm_mma_kernel(
    const __nv_bfloat16* __restrict__ Ah, const __nv_bfloat16* __restrict__ Al,
    const __nv_bfloat16* __restrict__ Bh, const __nv_bfloat16* __restrict__ Bl,
    int M, int Nc, int K,
    float* __restrict__ Cf, __nv_bfloat16* __restrict__ Ch, __nv_bfloat16* __restrict__ Cl,
    const float* __restrict__ bias, const float* __restrict__ resid, int mode) {
    extern __shared__ __nv_bfloat16 smp[];
    uint32_t sbase;
    asm("{ .reg .u64 t; cvta.to.shared.u64 t, %1; cvt.u32.u64 %0, t; }"
        : "=r"(sbase) : "l"(smp));

    const int tid = threadIdx.x;
    const int wid = tid >> 5, lane = tid & 31;
    const int g = lane >> 2, tig = lane & 3;
    const int wm = (wid >> 2) * 64;      // warp M offset (0,64)
    const int wn = (wid & 3) * 64;       // warp N offset (0,64,128,192)
    const int bm = blockIdx.y * 128, bn = blockIdx.x * 256;

    // staging coords: A has 512 16B transfers (2/thread), B has 1024 (4/thread)
    size_t aoff0[2], boff0[4];
    int a_so[2], b_so[4];
#pragma unroll
    for (int it = 0; it < 2; it++) {
        int idx = it * 256 + tid;
        int row = idx >> 2, c8 = (idx & 3) * 8;
        int gra = bm + row; if (gra > M - 1) gra = M - 1;
        aoff0[it] = (size_t)gra * K + c8;
        a_so[it] = row * LDT + c8;
    }
#pragma unroll
    for (int it = 0; it < 4; it++) {
        int idx = it * 256 + tid;
        int row = idx >> 2, c8 = (idx & 3) * 8;
        int grb = bn + row; if (grb > Nc - 1) grb = Nc - 1;
        boff0[it] = (size_t)grb * K + c8;
        b_so[it] = row * LDT + c8;
    }

    float acc[4][8][4];
#pragma unroll
    for (int i = 0; i < 4; i++)
#pragma unroll
        for (int j = 0; j < 8; j++)
#pragma unroll
            for (int k = 0; k < 4; k++) acc[i][j][k] = 0.f;

    const int nchunk = K / KC;

    // ---- stage chunk 0 into buffer 0 ----
#pragma unroll
    for (int it = 0; it < 2; it++) {
        uint32_t so = sbase + (uint32_t)a_so[it] * 2;
        cp_async16(so, Ah + aoff0[it]);
        cp_async16(so + TSZ_A * 2, Al + aoff0[it]);
    }
#pragma unroll
    for (int it = 0; it < 4; it++) {
        uint32_t so = sbase + (uint32_t)(2 * TSZ_A + b_so[it]) * 2;
        cp_async16(so, Bh + boff0[it]);
        cp_async16(so + TSZ_B * 2, Bl + boff0[it]);
    }
    CP_COMMIT();

    for (int c = 0; c < nchunk; c++) {
        if (c + 1 < nchunk) {
            int kb = (c + 1) * KC;
            uint32_t stb = sbase + (uint32_t)(((c + 1) & 1) * STG) * 2;
#pragma unroll
            for (int it = 0; it < 2; it++) {
                uint32_t so = stb + (uint32_t)a_so[it] * 2;
                cp_async16(so, Ah + aoff0[it] + kb);
                cp_async16(so + TSZ_A * 2, Al + aoff0[it] + kb);
            }
#pragma unroll
            for (int it = 0; it < 4; it++) {
                uint32_t so = stb + (uint32_t)(2 * TSZ_A + b_so[it]) * 2;
                cp_async16(so, Bh + boff0[it] + kb);
                cp_async16(so + TSZ_B * 2, Bl + boff0[it] + kb);
            }
            CP_COMMIT();
            CP_WAIT1();
        } else {
            CP_WAIT0();
        }
        __syncthreads();

        const __nv_bfloat16* sAh = smp + (c & 1) * STG;
        const __nv_bfloat16* sAl = sAh + TSZ_A;
        const __nv_bfloat16* sBh = sAh + 2 * TSZ_A;
        const __nv_bfloat16* sBl = sBh + TSZ_B;

#pragma unroll
        for (int ks = 0; ks < 2; ks++) {
            const int kk = ks * 16 + tig * 2;
            uint32_t ah[4][4], al[4][4];
#pragma unroll
            for (int mt = 0; mt < 4; mt++) {
                int r0 = (wm + mt * 16 + g) * LDT;
                int r1 = r0 + 8 * LDT;
                ah[mt][0] = *(const uint32_t*)&sAh[r0 + kk];
                ah[mt][1] = *(const uint32_t*)&sAh[r1 + kk];
                ah[mt][2] = *(const uint32_t*)&sAh[r0 + kk + 8];
                ah[mt][3] = *(const uint32_t*)&sAh[r1 + kk + 8];
                al[mt][0] = *(const uint32_t*)&sAl[r0 + kk];
                al[mt][1] = *(const uint32_t*)&sAl[r1 + kk];
                al[mt][2] = *(const uint32_t*)&sAl[r0 + kk + 8];
                al[mt][3] = *(const uint32_t*)&sAl[r1 + kk + 8];
            }
#pragma unroll
            for (int nt = 0; nt < 8; nt++) {
                int nrow = (wn + nt * 8 + g) * LDT;
                uint32_t bh0 = *(const uint32_t*)&sBh[nrow + kk];
                uint32_t bh1 = *(const uint32_t*)&sBh[nrow + kk + 8];
                uint32_t bl0 = *(const uint32_t*)&sBl[nrow + kk];
                uint32_t bl1 = *(const uint32_t*)&sBl[nrow + kk + 8];
#pragma unroll
                for (int mt = 0; mt < 4; mt++) {
                    mma16816(acc[mt][nt], ah[mt][0], ah[mt][1], ah[mt][2], ah[mt][3], bh0, bh1);
                    mma16816(acc[mt][nt], ah[mt][0], ah[mt][1], ah[mt][2], ah[mt][3], bl0, bl1);
                    mma16816(acc[mt][nt], al[mt][0], al[mt][1], al[mt][2], al[mt][3], bh0, bh1);
                }
            }
        }
        __syncthreads();
    }

    // ---- epilogue ----
#pragma unroll
    for (int mt = 0; mt < 4; mt++) {
        int row0 = bm + wm + mt * 16 + g;
        int row1 = row0 + 8;
#pragma unroll
        for (int nt = 0; nt < 8; nt++) {
            int col = bn + wn + nt * 8 + tig * 2;
#pragma unroll
            for (int half = 0; half < 2; half++) {
                int row = half ? row1 : row0;
                if (row >= M) continue;
                float v0 = acc[mt][nt][half * 2 + 0];
                float v1 = acc[mt][nt][half * 2 + 1];
                size_t idx = (size_t)row * Nc + col;
                if (mode == 0) {
                    Cf[idx] = v0; Cf[idx + 1] = v1;
                } else if (mode == 1) {
                    v0 = fmaxf(v0 + bias[col], 0.f);
                    v1 = fmaxf(v1 + bias[col + 1], 0.f);
                    __nv_bfloat16 h0 = __float2bfloat16(v0);
                    __nv_bfloat16 h1 = __float2bfloat16(v1);
                    Ch[idx] = h0; Ch[idx + 1] = h1;
                    Cl[idx] = __float2bfloat16(v0 - __bfloat162float(h0));
                    Cl[idx + 1] = __float2bfloat16(v1 - __bfloat162float(h1));
                } else {
                    Cf[idx] = v0 + bias[col] + resid[idx];
                    Cf[idx + 1] = v1 + bias[col + 1] + resid[idx + 1];
                }
            }
        }
    }
}

// ======================= edge attention + softmax (warp per dst node) =======================
// fh rows at g_proj[s*768 + 0..255], ftl at g_proj[v*768 + 256..511]
__global__ void __launch_bounds__(256) attn_kernel(const float* __restrict__ attnv) {
    __shared__ float sh_e[8][MAXD][8];
    int w = threadIdx.x >> 5;
    int lane = threadIdx.x & 31;
    int v = blockIdx.x * 8 + w;
    if (v >= N_NODES) return;

    float ftl_v[8], at[8];
#pragma unroll
    for (int h = 0; h < 8; h++) {
        ftl_v[h] = g_proj[(size_t)v * PSTRIDE + 256 + h * 32 + lane];
        at[h] = attnv[h * 32 + lane];
    }
    float ld = g_logdeg[v];
    int s0 = g_rowptr[v], s1 = g_rowptr[v + 1];
    int cnt = s1 - s0;
    int cc = cnt < MAXD ? cnt : MAXD;

    float m8[8];
#pragma unroll
    for (int h = 0; h < 8; h++) m8[h] = -1e30f;

    for (int q = 0; q < cc; q++) {
        int p = s0 + q;
        int s = g_csr_src[p], rr = g_csr_rid[p];
        const float* fhp = &g_proj[(size_t)s * PSTRIDE + lane];
        const float* frp = &g_fr[(size_t)rr * F_DIM + lane];
#pragma unroll
        for (int h = 0; h < 8; h++) {
            float x = fhp[h * 32] * ftl_v[h] * frp[h * 32];
            x = x > 0.f ? x : SLOPE * x;
            float e = x * at[h];
#pragma unroll
            for (int o = 16; o; o >>= 1) e += __shfl_xor_sync(0xFFFFFFFFu, e, o);
            e *= ld;
            m8[h] = fmaxf(m8[h], e);
            if (lane == h) sh_e[w][q][h] = e;
        }
    }
    __syncwarp();

    float s8[8];
#pragma unroll
    for (int h = 0; h < 8; h++) s8[h] = 0.f;
    for (int q = lane; q < cc; q += 32) {
#pragma unroll
        for (int h = 0; h < 8; h++) {
            float ex = expf(sh_e[w][q][h] - m8[h]);
            sh_e[w][q][h] = ex;
            s8[h] += ex;
        }
    }
#pragma unroll
    for (int h = 0; h < 8; h++) {
        float t = s8[h];
#pragma unroll
        for (int o = 16; o; o >>= 1) t += __shfl_xor_sync(0xFFFFFFFFu, t, o);
        s8[h] = 1.0f / t;
    }
    __syncwarp();
    for (int q = lane; q < cc; q += 32) {
        int p = s0 + q;
        float4 o0, o1;
        o0.x = sh_e[w][q][0] * s8[0]; o0.y = sh_e[w][q][1] * s8[1];
        o0.z = sh_e[w][q][2] * s8[2]; o0.w = sh_e[w][q][3] * s8[3];
        o1.x = sh_e[w][q][4] * s8[4]; o1.y = sh_e[w][q][5] * s8[5];
        o1.z = sh_e[w][q][6] * s8[6]; o1.w = sh_e[w][q][7] * s8[7];
        *(float4*)&g_a[(size_t)p * 8] = o0;
        *(float4*)&g_a[(size_t)p * 8 + 4] = o1;
    }
}

// ======================= PPR hop (warp per dst node; atomic-free via CSR) =======================
// fen (feat0) at g_proj[v*768 + 512 + ...]; fin has row stride fstride.
__global__ void __launch_bounds__(256) hop_kernel(const float* __restrict__ fin, int fstride,
                                                  float* __restrict__ fout,
                                                  const float* __restrict__ ent, int addent) {
    int w = threadIdx.x >> 5, lane = threadIdx.x & 31;
    int v = blockIdx.x * 8 + w;
    if (v >= N_NODES) return;
    int s0 = g_rowptr[v], s1 = g_rowptr[v + 1];
    float acc[8] = {0.f, 0.f, 0.f, 0.f, 0.f, 0.f, 0.f, 0.f};
    for (int p = s0; p < s1; p++) {
        int s = g_csr_src[p];
        const float4* ap = (const float4*)&g_a[(size_t)p * 8];
        float4 a0 = ap[0], a1 = ap[1];
        const float* f = fin + (size_t)s * fstride + lane;
        acc[0] += f[0]   * a0.x; acc[1] += f[32]  * a0.y;
        acc[2] += f[64]  * a0.z; acc[3] += f[96]  * a0.w;
        acc[4] += f[128] * a1.x; acc[5] += f[160] * a1.y;
        acc[6] += f[192] * a1.z; acc[7] += f[224] * a1.w;
    }
    size_t base = (size_t)v * F_DIM + lane;
    size_t pbase = (size_t)v * PSTRIDE + 512 + lane;
#pragma unroll
    for (int h = 0; h < 8; h++) {
        float r = 0.9f * acc[h] + 0.1f * g_proj[pbase + h * 32];
        if (addent) r += ent[base + h * 32];
        fout[base + h * 32] = r;
    }
}

// ======================= launch =======================
extern "C" void kernel_launch(void* const* d_in, const int* in_sizes, int n_in,
                              void* d_out, int out_size) {
    const float* ent    = (const float*)d_in[0];
    const float* rel    = (const float*)d_in[1];
    const float* W_head = (const float*)d_in[2];
    const float* W_tail = (const float*)d_in[3];
    const float* W_ent  = (const float*)d_in[4];
    const float* W_rel  = (const float*)d_in[5];
    const float* attnv  = (const float*)d_in[6];
    const float* lne_g = (const float*)d_in[7];
    const float* lne_b = (const float*)d_in[8];
    const float* lnr_g = (const float*)d_in[9];
    const float* lnr_b = (const float*)d_in[10];
    const float* lnf_g = (const float*)d_in[11];
    const float* lnf_b = (const float*)d_in[12];
    const float* W1 = (const float*)d_in[13];
    const float* b1 = (const float*)d_in[14];
    const float* W2 = (const float*)d_in[15];
    const float* b2 = (const float*)d_in[16];
    const int* src = (const int*)d_in[17];
    const int* dst = (const int*)d_in[18];
    const int* rid = (const int*)d_in[19];
    float* out = (float*)d_out;

    float *pproj, *pfr, *pfeat, *pfeat2, *prst;
    cudaGetSymbolAddress((void**)&pproj, g_proj);
    cudaGetSymbolAddress((void**)&pfr, g_fr);
    cudaGetSymbolAddress((void**)&pfeat, g_feat);
    cudaGetSymbolAddress((void**)&pfeat2, g_feat2);
    cudaGetSymbolAddress((void**)&prst, g_rst);

    __nv_bfloat16 *pxh, *pxl, *prh, *prl, *pyh, *pyl, *phh, *phl;
    cudaGetSymbolAddress((void**)&pxh, g_xh);
    cudaGetSymbolAddress((void**)&pxl, g_xl);
    cudaGetSymbolAddress((void**)&prh, g_rh);
    cudaGetSymbolAddress((void**)&prl, g_rl);
    cudaGetSymbolAddress((void**)&pyh, g_yh);
    cudaGetSymbolAddress((void**)&pyl, g_yl);
    cudaGetSymbolAddress((void**)&phh, g_hidh);
    cudaGetSymbolAddress((void**)&phl, g_hidl);

    __nv_bfloat16 *pWph, *pWpl, *pWrh, *pWrl, *pW1h, *pW1l, *pW2h, *pW2l;
    cudaGetSymbolAddress((void**)&pWph, g_Wph); cudaGetSymbolAddress((void**)&pWpl, g_Wpl);
    cudaGetSymbolAddress((void**)&pWrh, g_Wrh); cudaGetSymbolAddress((void**)&pWrl, g_Wrl);
    cudaGetSymbolAddress((void**)&pW1h, g_W1h); cudaGetSymbolAddress((void**)&pW1l, g_W1l);
    cudaGetSymbolAddress((void**)&pW2h, g_W2h); cudaGetSymbolAddress((void**)&pW2l, g_W2l);

    cudaFuncSetAttribute(gemm_mma_kernel, cudaFuncAttributeMaxDynamicSharedMemorySize, GEMM_SMEM);

    // CSR build
    zero_counts_kernel<<<(N_NODES + 255) / 256, 256>>>();
    count_kernel<<<(N_EDGES + 255) / 256, 256>>>(dst);
    scan_kernel<<<1, 1024>>>();
    scatter_kernel<<<(N_EDGES + 255) / 256, 256>>>(src, dst, rid);

    // LayerNorms -> bf16 splits
    ln_split_kernel<<<N_NODES, 256>>>(ent, lne_g, lne_b, pxh, pxl);
    ln_split_kernel<<<N_REL, 256>>>(rel, lnr_g, lnr_b, prh, prl);

    // weight transposes + splits (head/tail/ent fused into one [768,256] buffer)
    dim3 tb(32, 8);
    trans_split_kernel<<<dim3(F_DIM / 32, F_DIM / 32), tb>>>(W_head, F_DIM, F_DIM,
                                                             pWph + 0 * F_DIM * F_DIM,
                                                             pWpl + 0 * F_DIM * F_DIM);
    trans_split_kernel<<<dim3(F_DIM / 32, F_DIM / 32), tb>>>(W_tail, F_DIM, F_DIM,
                                                             pWph + 1 * F_DIM * F_DIM,
                                                             pWpl + 1 * F_DIM * F_DIM);
    trans_split_kernel<<<dim3(F_DIM / 32, F_DIM / 32), tb>>>(W_ent,  F_DIM, F_DIM,
                                                             pWph + 2 * F_DIM * F_DIM,
                                                             pWpl + 2 * F_DIM * F_DIM);
    trans_split_kernel<<<dim3(F_DIM / 32, F_DIM / 32), tb>>>(W_rel,  F_DIM, F_DIM, pWrh, pWrl);
    trans_split_kernel<<<dim3(FF_DIM / 32, F_DIM / 32), tb>>>(W1, F_DIM, FF_DIM, pW1h, pW1l);
    trans_split_kernel<<<dim3(F_DIM / 32, FF_DIM / 32), tb>>>(W2, FF_DIM, F_DIM, pW2h, pW2l);

    // fused projection GEMM: [20000,256] @ [768,256]^T -> g_proj
    int mby = (N_NODES + 127) / 128;
    dim3 gP(PSTRIDE / 256, mby);
    gemm_mma_kernel<<<gP, 256, GEMM_SMEM>>>(pxh, pxl, pWph, pWpl, N_NODES, PSTRIDE, F_DIM,
                                            pproj, nullptr, nullptr, nullptr, nullptr, 0);
    dim3 gR(1, 1);
    gemm_mma_kernel<<<gR, 256, GEMM_SMEM>>>(prh, prl, pWrh, pWrl, N_REL, F_DIM, F_DIM,
                                            pfr, nullptr, nullptr, nullptr, nullptr, 0);

    // attention + softmax
    attn_kernel<<<(N_NODES + 7) / 8, 256>>>(attnv);

    // 5 PPR hops (last fuses + ent_feat residual into rst)
    int nb = (N_NODES + 7) / 8;
    hop_kernel<<<nb, 256>>>(pproj + 512, PSTRIDE, pfeat, nullptr, 0);
    hop_kernel<<<nb, 256>>>(pfeat, F_DIM, pfeat2, nullptr, 0);
    hop_kernel<<<nb, 256>>>(pfeat2, F_DIM, pfeat, nullptr, 0);
    hop_kernel<<<nb, 256>>>(pfeat, F_DIM, pfeat2, nullptr, 0);
    hop_kernel<<<nb, 256>>>(pfeat2, F_DIM, prst, ent, 1);

    // FFN
    ln_split_kernel<<<N_NODES, 256>>>(prst, lnf_g, lnf_b, pyh, pyl);
    dim3 gH(FF_DIM / 256, mby);
    gemm_mma_kernel<<<gH, 256, GEMM_SMEM>>>(pyh, pyl, pW1h, pW1l, N_NODES, FF_DIM, F_DIM,
                                            nullptr, phh, phl, b1, nullptr, 1);
    dim3 gO(F_DIM / 256 + 1, mby);
    gemm_mma_kernel<<<dim3(1, mby), 256, GEMM_SMEM>>>(phh, phl, pW2h, pW2l, N_NODES, F_DIM, FF_DIM,
                                                      out, nullptr, nullptr, b2, prst, 2);
}

// round 13
// speedup vs baseline: 1.0708x; 1.0708x over previous
#include <cuda_runtime.h>
#include <cuda_bf16.h>
#include <math.h>
#include <stdint.h>

#define N_NODES 20000
#define N_EDGES 320000
#define N_REL   100
#define F_DIM   256
#define FF_DIM  1024
#define H_HEADS 8
#define D_HEAD  32
#define SLOPE   0.2f
#define MAXD    128
#define PSTRIDE 768   // fused projection row stride [fh | ftl | fen]

// ======================= scratch (static device globals) =======================
__device__ __align__(16) float g_proj[N_NODES * PSTRIDE];   // [fh|ftl|fen]
__device__ __align__(16) float g_fr[N_REL * F_DIM];
__device__ int   g_deg[N_NODES];
__device__ int   g_cursor[N_NODES];
__device__ int   g_rowptr[N_NODES + 1];
__device__ float g_logdeg[N_NODES];
__device__ int   g_csr_src[N_EDGES];
__device__ int   g_csr_rid[N_EDGES];
__device__ __align__(16) float g_a[N_EDGES * H_HEADS];
__device__ __align__(16) float g_feat[N_NODES * F_DIM];
__device__ __align__(16) float g_feat2[N_NODES * F_DIM];
__device__ __align__(16) float g_rst[N_NODES * F_DIM];

// bf16 split activations
__device__ __align__(16) __nv_bfloat16 g_xh[N_NODES * F_DIM];
__device__ __align__(16) __nv_bfloat16 g_xl[N_NODES * F_DIM];
__device__ __align__(16) __nv_bfloat16 g_rh[N_REL * F_DIM];
__device__ __align__(16) __nv_bfloat16 g_rl[N_REL * F_DIM];
__device__ __align__(16) __nv_bfloat16 g_yh[N_NODES * F_DIM];
__device__ __align__(16) __nv_bfloat16 g_yl[N_NODES * F_DIM];
__device__ __align__(16) __nv_bfloat16 g_hidh[N_NODES * FF_DIM];
__device__ __align__(16) __nv_bfloat16 g_hidl[N_NODES * FF_DIM];

// bf16 split + transposed weights [N,K] K-major
__device__ __align__(16) __nv_bfloat16 g_Wph[3 * F_DIM * F_DIM], g_Wpl[3 * F_DIM * F_DIM]; // fused proj
__device__ __align__(16) __nv_bfloat16 g_Wrh[F_DIM * F_DIM], g_Wrl[F_DIM * F_DIM];
__device__ __align__(16) __nv_bfloat16 g_W1h[FF_DIM * F_DIM], g_W1l[FF_DIM * F_DIM];
__device__ __align__(16) __nv_bfloat16 g_W2h[F_DIM * FF_DIM], g_W2l[F_DIM * FF_DIM];

// ======================= CSR build =======================
__global__ void count_kernel(const int* __restrict__ dst) {
    int e = blockIdx.x * 256 + threadIdx.x;
    if (e < N_EDGES) atomicAdd(&g_deg[dst[e]], 1);
}
__global__ void scan_kernel() {
    __shared__ int sh[1024];
    __shared__ int carry_s;
    int t = threadIdx.x;
    if (t == 0) carry_s = 0;
    __syncthreads();
    for (int base = 0; base < N_NODES; base += 1024) {
        int i = base + t;
        int v = (i < N_NODES) ? g_deg[i] : 0;
        sh[t] = v;
        __syncthreads();
        for (int o = 1; o < 1024; o <<= 1) {
            int tmp = (t >= o) ? sh[t - o] : 0;
            __syncthreads();
            sh[t] += tmp;
            __syncthreads();
        }
        int incl = sh[t];
        if (i < N_NODES) {
            g_rowptr[i] = carry_s + incl - v;
            g_logdeg[i] = logf((float)v) * (1.0f / (float)D_HEAD);
        }
        __syncthreads();
        if (t == 1023) carry_s += incl;
        __syncthreads();
    }
    if (t == 0) g_rowptr[N_NODES] = N_EDGES;
}
__global__ void scatter_kernel(const int* __restrict__ src, const int* __restrict__ dst,
                               const int* __restrict__ rid) {
    int e = blockIdx.x * 256 + threadIdx.x;
    if (e < N_EDGES) {
        int d = dst[e];
        int p = g_rowptr[d] + atomicAdd(&g_cursor[d], 1);
        g_csr_src[p] = src[e];
        g_csr_rid[p] = rid[e];
    }
}

// ======================= LayerNorm -> bf16 hi/lo split =======================
__global__ void ln_split_kernel(const float* __restrict__ in, const float* __restrict__ gg,
                                const float* __restrict__ bb,
                                __nv_bfloat16* __restrict__ oh, __nv_bfloat16* __restrict__ ol) {
    int row = blockIdx.x;
    int t = threadIdx.x;
    const float* x = in + (size_t)row * F_DIM;
    float v = x[t];
    float s = v, s2 = v * v;
#pragma unroll
    for (int o = 16; o; o >>= 1) {
        s  += __shfl_xor_sync(0xFFFFFFFFu, s, o);
        s2 += __shfl_xor_sync(0xFFFFFFFFu, s2, o);
    }
    __shared__ float sh[8], sh2[8];
    int w = t >> 5, l = t & 31;
    if (l == 0) { sh[w] = s; sh2[w] = s2; }
    __syncthreads();
    if (w == 0) {
        float a = (l < 8) ? sh[l] : 0.f;
        float a2 = (l < 8) ? sh2[l] : 0.f;
#pragma unroll
        for (int o = 4; o; o >>= 1) {
            a  += __shfl_xor_sync(0xFFFFFFFFu, a, o);
            a2 += __shfl_xor_sync(0xFFFFFFFFu, a2, o);
        }
        if (l == 0) { sh[0] = a; sh2[0] = a2; }
    }
    __syncthreads();
    float mean = sh[0] * (1.0f / F_DIM);
    float var = sh2[0] * (1.0f / F_DIM) - mean * mean;
    float inv = rsqrtf(var + 1e-5f);
    float r = (v - mean) * inv * gg[t] + bb[t];
    __nv_bfloat16 h = __float2bfloat16(r);
    size_t idx = (size_t)row * F_DIM + t;
    oh[idx] = h;
    ol[idx] = __float2bfloat16(r - __bfloat162float(h));
}

// ======================= weight transpose + split: W[K,N] -> Wt[N,K] bf16 hi/lo =======================
__global__ void trans_split_kernel(const float* __restrict__ W, int K, int Nc,
                                   __nv_bfloat16* __restrict__ Th, __nv_bfloat16* __restrict__ Tl) {
    __shared__ float t[32][33];
    int n0 = blockIdx.x * 32, k0 = blockIdx.y * 32;
    int tx = threadIdx.x, ty = threadIdx.y;  // 32 x 8
#pragma unroll
    for (int j = 0; j < 32; j += 8)
        t[ty + j][tx] = W[(size_t)(k0 + ty + j) * Nc + n0 + tx];
    __syncthreads();
#pragma unroll
    for (int j = 0; j < 32; j += 8) {
        float v = t[tx][ty + j];
        int n = n0 + ty + j, k = k0 + tx;
        __nv_bfloat16 h = __float2bfloat16(v);
        Th[(size_t)n * K + k] = h;
        Tl[(size_t)n * K + k] = __float2bfloat16(v - __bfloat162float(h));
    }
}

// ======================= HMMA GEMM (cp.async double-buffered, 128x128 tile) =======================
// C[M,Nc] = A[M,K] @ Wt[Nc,K]^T, mma.sync m16n8k16 bf16, 3-term split (fp32 accum).
// CTA: 256 thr / 8 warps, warp tile 32x64, K-chunk 32, 2-stage pipeline, 2 CTAs/SM.
// mode 0: C=fp32. mode 1: +bias, relu -> Ch/Cl bf16 split. mode 2: +bias+resid -> fp32.

#define KC 32
#define LDT 40                 // smem row stride in bf16 (KC + 8 pad)
#define TSZ (128 * LDT)        // bf16 elems per tile
#define STG (4 * TSZ)          // bf16 elems per stage
#define GEMM_SMEM (2 * STG * 2)  // bytes (2 stages)

__device__ __forceinline__ void mma16816(float* c, uint32_t a0, uint32_t a1, uint32_t a2,
                                         uint32_t a3, uint32_t b0, uint32_t b1) {
    asm volatile(
        "mma.sync.aligned.m16n8k16.row.col.f32.bf16.bf16.f32 "
        "{%0,%1,%2,%3}, {%4,%5,%6,%7}, {%8,%9}, {%0,%1,%2,%3};"
        : "+f"(c[0]), "+f"(c[1]), "+f"(c[2]), "+f"(c[3])
        : "r"(a0), "r"(a1), "r"(a2), "r"(a3), "r"(b0), "r"(b1));
}

__device__ __forceinline__ void cp_async16(uint32_t saddr, const void* gptr) {
    asm volatile("cp.async.cg.shared.global [%0], [%1], 16;" :: "r"(saddr), "l"(gptr));
}
#define CP_COMMIT() asm volatile("cp.async.commit_group;" ::: "memory")
#define CP_WAIT0()  asm volatile("cp.async.wait_group 0;" ::: "memory")
#define CP_WAIT1()  asm volatile("cp.async.wait_group 1;" ::: "memory")

__global__ void __launch_bounds__(256, 2) gemm_mma_kernel(
    const __nv_bfloat16* __restrict__ Ah, const __nv_bfloat16* __restrict__ Al,
    const __nv_bfloat16* __restrict__ Bh, const __nv_bfloat16* __restrict__ Bl,
    int M, int Nc, int K,
    float* __restrict__ Cf, __nv_bfloat16* __restrict__ Ch, __nv_bfloat16* __restrict__ Cl,
    const float* __restrict__ bias, const float* __restrict__ resid, int mode) {
    extern __shared__ __nv_bfloat16 smp[];
    uint32_t sbase;
    asm("{ .reg .u64 t; cvta.to.shared.u64 t, %1; cvt.u32.u64 %0, t; }"
        : "=r"(sbase) : "l"(smp));

    const int tid = threadIdx.x;
    const int wid = tid >> 5, lane = tid & 31;
    const int g = lane >> 2, tig = lane & 3;
    const int wm = (wid >> 1) * 32;     // warp M offset (0,32,64,96)
    const int wn = (wid & 1) * 64;      // warp N offset (0,64)
    const int bm = blockIdx.y * 128, bn = blockIdx.x * 128;

    // per-thread staging coords (2 halves of 512 transfers)
    int s_row[2], s_c8[2];
    size_t aoff0[2], boff0[2];
#pragma unroll
    for (int half = 0; half < 2; half++) {
        int idx = half * 256 + tid;      // 0..511
        int row = idx >> 2;
        int c8 = (idx & 3) * 8;
        s_row[half] = row;
        s_c8[half] = c8;
        int gra = bm + row; if (gra > M - 1) gra = M - 1;
        int grb = bn + row; if (grb > Nc - 1) grb = Nc - 1;
        aoff0[half] = (size_t)gra * K + c8;
        boff0[half] = (size_t)grb * K + c8;
    }

    float acc[2][8][4];
#pragma unroll
    for (int i = 0; i < 2; i++)
#pragma unroll
        for (int j = 0; j < 8; j++)
#pragma unroll
            for (int k = 0; k < 4; k++) acc[i][j][k] = 0.f;

    const int nchunk = K / KC;

    // ---- stage chunk 0 into buffer 0 ----
#pragma unroll
    for (int half = 0; half < 2; half++) {
        uint32_t so = sbase + (uint32_t)(s_row[half] * LDT + s_c8[half]) * 2;
        cp_async16(so + 0 * TSZ * 2, Ah + aoff0[half]);
        cp_async16(so + 1 * TSZ * 2, Al + aoff0[half]);
        cp_async16(so + 2 * TSZ * 2, Bh + boff0[half]);
        cp_async16(so + 3 * TSZ * 2, Bl + boff0[half]);
    }
    CP_COMMIT();

    for (int c = 0; c < nchunk; c++) {
        // issue next chunk into the other buffer, then wait for current
        if (c + 1 < nchunk) {
            int kb = (c + 1) * KC;
            uint32_t stb = sbase + (uint32_t)(((c + 1) & 1) * STG) * 2;
#pragma unroll
            for (int half = 0; half < 2; half++) {
                uint32_t so = stb + (uint32_t)(s_row[half] * LDT + s_c8[half]) * 2;
                cp_async16(so + 0 * TSZ * 2, Ah + aoff0[half] + kb);
                cp_async16(so + 1 * TSZ * 2, Al + aoff0[half] + kb);
                cp_async16(so + 2 * TSZ * 2, Bh + boff0[half] + kb);
                cp_async16(so + 3 * TSZ * 2, Bl + boff0[half] + kb);
            }
            CP_COMMIT();
            CP_WAIT1();
        } else {
            CP_WAIT0();
        }
        __syncthreads();

        const __nv_bfloat16* sAh = smp + (c & 1) * STG;
        const __nv_bfloat16* sAl = sAh + TSZ;
        const __nv_bfloat16* sBh = sAh + 2 * TSZ;
        const __nv_bfloat16* sBl = sAh + 3 * TSZ;

#pragma unroll
        for (int ks = 0; ks < 2; ks++) {
            const int kk = ks * 16 + tig * 2;
            uint32_t ah[2][4], al[2][4];
#pragma unroll
            for (int mt = 0; mt < 2; mt++) {
                int r0 = (wm + mt * 16 + g) * LDT;
                int r1 = r0 + 8 * LDT;
                ah[mt][0] = *(const uint32_t*)&sAh[r0 + kk];
                ah[mt][1] = *(const uint32_t*)&sAh[r1 + kk];
                ah[mt][2] = *(const uint32_t*)&sAh[r0 + kk + 8];
                ah[mt][3] = *(const uint32_t*)&sAh[r1 + kk + 8];
                al[mt][0] = *(const uint32_t*)&sAl[r0 + kk];
                al[mt][1] = *(const uint32_t*)&sAl[r1 + kk];
                al[mt][2] = *(const uint32_t*)&sAl[r0 + kk + 8];
                al[mt][3] = *(const uint32_t*)&sAl[r1 + kk + 8];
            }
#pragma unroll
            for (int nt = 0; nt < 8; nt++) {
                int nrow = (wn + nt * 8 + g) * LDT;
                uint32_t bh0 = *(const uint32_t*)&sBh[nrow + kk];
                uint32_t bh1 = *(const uint32_t*)&sBh[nrow + kk + 8];
                uint32_t bl0 = *(const uint32_t*)&sBl[nrow + kk];
                uint32_t bl1 = *(const uint32_t*)&sBl[nrow + kk + 8];
#pragma unroll
                for (int mt = 0; mt < 2; mt++) {
                    mma16816(acc[mt][nt], ah[mt][0], ah[mt][1], ah[mt][2], ah[mt][3], bh0, bh1);
                    mma16816(acc[mt][nt], ah[mt][0], ah[mt][1], ah[mt][2], ah[mt][3], bl0, bl1);
                    mma16816(acc[mt][nt], al[mt][0], al[mt][1], al[mt][2], al[mt][3], bh0, bh1);
                }
            }
        }
        __syncthreads();
    }

    // ---- epilogue ----
#pragma unroll
    for (int mt = 0; mt < 2; mt++) {
        int row0 = bm + wm + mt * 16 + g;
        int row1 = row0 + 8;
#pragma unroll
        for (int nt = 0; nt < 8; nt++) {
            int col = bn + wn + nt * 8 + tig * 2;
#pragma unroll
            for (int half = 0; half < 2; half++) {
                int row = half ? row1 : row0;
                if (row >= M) continue;
                float v0 = acc[mt][nt][half * 2 + 0];
                float v1 = acc[mt][nt][half * 2 + 1];
                size_t idx = (size_t)row * Nc + col;
                if (mode == 0) {
                    Cf[idx] = v0; Cf[idx + 1] = v1;
                } else if (mode == 1) {
                    v0 = fmaxf(v0 + bias[col], 0.f);
                    v1 = fmaxf(v1 + bias[col + 1], 0.f);
                    __nv_bfloat16 h0 = __float2bfloat16(v0);
                    __nv_bfloat16 h1 = __float2bfloat16(v1);
                    Ch[idx] = h0; Ch[idx + 1] = h1;
                    Cl[idx] = __float2bfloat16(v0 - __bfloat162float(h0));
                    Cl[idx + 1] = __float2bfloat16(v1 - __bfloat162float(h1));
                } else {
                    Cf[idx] = v0 + bias[col] + resid[idx];
                    Cf[idx + 1] = v1 + bias[col + 1] + resid[idx + 1];
                }
            }
        }
    }
}

// ======================= edge attention + softmax (warp per dst node) =======================
// fh rows at g_proj[s*768 + 0..255], ftl at g_proj[v*768 + 256..511]
__global__ void __launch_bounds__(256) attn_kernel(const float* __restrict__ attnv) {
    __shared__ float sh_e[8][MAXD][8];
    int w = threadIdx.x >> 5;
    int lane = threadIdx.x & 31;
    int v = blockIdx.x * 8 + w;
    if (v >= N_NODES) return;

    float ftl_v[8], at[8];
#pragma unroll
    for (int h = 0; h < 8; h++) {
        ftl_v[h] = g_proj[(size_t)v * PSTRIDE + 256 + h * 32 + lane];
        at[h] = attnv[h * 32 + lane];
    }
    float ld = g_logdeg[v];
    int s0 = g_rowptr[v], s1 = g_rowptr[v + 1];
    int cnt = s1 - s0;
    int cc = cnt < MAXD ? cnt : MAXD;

    float m8[8];
#pragma unroll
    for (int h = 0; h < 8; h++) m8[h] = -1e30f;

    for (int q = 0; q < cc; q++) {
        int p = s0 + q;
        int s = g_csr_src[p], rr = g_csr_rid[p];
        const float* fhp = &g_proj[(size_t)s * PSTRIDE + lane];
        const float* frp = &g_fr[(size_t)rr * F_DIM + lane];
#pragma unroll
        for (int h = 0; h < 8; h++) {
            float x = __ldg(fhp + h * 32) * ftl_v[h] * __ldg(frp + h * 32);
            x = x > 0.f ? x : SLOPE * x;
            float e = x * at[h];
#pragma unroll
            for (int o = 16; o; o >>= 1) e += __shfl_xor_sync(0xFFFFFFFFu, e, o);
            e *= ld;
            m8[h] = fmaxf(m8[h], e);
            if (lane == h) sh_e[w][q][h] = e;
        }
    }
    __syncwarp();

    float s8[8];
#pragma unroll
    for (int h = 0; h < 8; h++) s8[h] = 0.f;
    for (int q = lane; q < cc; q += 32) {
#pragma unroll
        for (int h = 0; h < 8; h++) {
            float ex = expf(sh_e[w][q][h] - m8[h]);
            sh_e[w][q][h] = ex;
            s8[h] += ex;
        }
    }
#pragma unroll
    for (int h = 0; h < 8; h++) {
        float t = s8[h];
#pragma unroll
        for (int o = 16; o; o >>= 1) t += __shfl_xor_sync(0xFFFFFFFFu, t, o);
        s8[h] = 1.0f / t;
    }
    __syncwarp();
    for (int q = lane; q < cc; q += 32) {
        int p = s0 + q;
        float4 o0, o1;
        o0.x = sh_e[w][q][0] * s8[0]; o0.y = sh_e[w][q][1] * s8[1];
        o0.z = sh_e[w][q][2] * s8[2]; o0.w = sh_e[w][q][3] * s8[3];
        o1.x = sh_e[w][q][4] * s8[4]; o1.y = sh_e[w][q][5] * s8[5];
        o1.z = sh_e[w][q][6] * s8[6]; o1.w = sh_e[w][q][7] * s8[7];
        *(float4*)&g_a[(size_t)p * 8] = o0;
        *(float4*)&g_a[(size_t)p * 8 + 4] = o1;
    }
}

// ======================= PPR hop (warp per dst node; atomic-free via CSR) =======================
// fen (feat0) at g_proj[v*768 + 512 + ...]; fin has row stride fstride.
__global__ void __launch_bounds__(256) hop_kernel(const float* __restrict__ fin, int fstride,
                                                  float* __restrict__ fout,
                                                  const float* __restrict__ ent, int addent) {
    int w = threadIdx.x >> 5, lane = threadIdx.x & 31;
    int v = blockIdx.x * 8 + w;
    if (v >= N_NODES) return;
    int s0 = g_rowptr[v], s1 = g_rowptr[v + 1];
    float acc[8] = {0.f, 0.f, 0.f, 0.f, 0.f, 0.f, 0.f, 0.f};
    for (int p = s0; p < s1; p++) {
        int s = g_csr_src[p];
        const float4* ap = (const float4*)&g_a[(size_t)p * 8];
        float4 a0 = __ldg(ap), a1 = __ldg(ap + 1);
        const float* f = fin + (size_t)s * fstride + lane;
        acc[0] += __ldg(f)       * a0.x; acc[1] += __ldg(f + 32)  * a0.y;
        acc[2] += __ldg(f + 64)  * a0.z; acc[3] += __ldg(f + 96)  * a0.w;
        acc[4] += __ldg(f + 128) * a1.x; acc[5] += __ldg(f + 160) * a1.y;
        acc[6] += __ldg(f + 192) * a1.z; acc[7] += __ldg(f + 224) * a1.w;
    }
    size_t base = (size_t)v * F_DIM + lane;
    size_t pbase = (size_t)v * PSTRIDE + 512 + lane;
#pragma unroll
    for (int h = 0; h < 8; h++) {
        float r = 0.9f * acc[h] + 0.1f * g_proj[pbase + h * 32];
        if (addent) r += ent[base + h * 32];
        fout[base + h * 32] = r;
    }
}

// ======================= launch =======================
extern "C" void kernel_launch(void* const* d_in, const int* in_sizes, int n_in,
                              void* d_out, int out_size) {
    const float* ent    = (const float*)d_in[0];
    const float* rel    = (const float*)d_in[1];
    const float* W_head = (const float*)d_in[2];
    const float* W_tail = (const float*)d_in[3];
    const float* W_ent  = (const float*)d_in[4];
    const float* W_rel  = (const float*)d_in[5];
    const float* attnv  = (const float*)d_in[6];
    const float* lne_g = (const float*)d_in[7];
    const float* lne_b = (const float*)d_in[8];
    const float* lnr_g = (const float*)d_in[9];
    const float* lnr_b = (const float*)d_in[10];
    const float* lnf_g = (const float*)d_in[11];
    const float* lnf_b = (const float*)d_in[12];
    const float* W1 = (const float*)d_in[13];
    const float* b1 = (const float*)d_in[14];
    const float* W2 = (const float*)d_in[15];
    const float* b2 = (const float*)d_in[16];
    const int* src = (const int*)d_in[17];
    const int* dst = (const int*)d_in[18];
    const int* rid = (const int*)d_in[19];
    float* out = (float*)d_out;

    float *pproj, *pfr, *pfeat, *pfeat2, *prst;
    cudaGetSymbolAddress((void**)&pproj, g_proj);
    cudaGetSymbolAddress((void**)&pfr, g_fr);
    cudaGetSymbolAddress((void**)&pfeat, g_feat);
    cudaGetSymbolAddress((void**)&pfeat2, g_feat2);
    cudaGetSymbolAddress((void**)&prst, g_rst);

    int *pdeg, *pcursor;
    cudaGetSymbolAddress((void**)&pdeg, g_deg);
    cudaGetSymbolAddress((void**)&pcursor, g_cursor);

    __nv_bfloat16 *pxh, *pxl, *prh, *prl, *pyh, *pyl, *phh, *phl;
    cudaGetSymbolAddress((void**)&pxh, g_xh);
    cudaGetSymbolAddress((void**)&pxl, g_xl);
    cudaGetSymbolAddress((void**)&prh, g_rh);
    cudaGetSymbolAddress((void**)&prl, g_rl);
    cudaGetSymbolAddress((void**)&pyh, g_yh);
    cudaGetSymbolAddress((void**)&pyl, g_yl);
    cudaGetSymbolAddress((void**)&phh, g_hidh);
    cudaGetSymbolAddress((void**)&phl, g_hidl);

    __nv_bfloat16 *pWph, *pWpl, *pWrh, *pWrl, *pW1h, *pW1l, *pW2h, *pW2l;
    cudaGetSymbolAddress((void**)&pWph, g_Wph); cudaGetSymbolAddress((void**)&pWpl, g_Wpl);
    cudaGetSymbolAddress((void**)&pWrh, g_Wrh); cudaGetSymbolAddress((void**)&pWrl, g_Wrl);
    cudaGetSymbolAddress((void**)&pW1h, g_W1h); cudaGetSymbolAddress((void**)&pW1l, g_W1l);
    cudaGetSymbolAddress((void**)&pW2h, g_W2h); cudaGetSymbolAddress((void**)&pW2l, g_W2l);

    cudaFuncSetAttribute(gemm_mma_kernel, cudaFuncAttributeMaxDynamicSharedMemorySize, GEMM_SMEM);

    // CSR build
    cudaMemsetAsync(pdeg, 0, N_NODES * sizeof(int));
    cudaMemsetAsync(pcursor, 0, N_NODES * sizeof(int));
    count_kernel<<<(N_EDGES + 255) / 256, 256>>>(dst);
    scan_kernel<<<1, 1024>>>();
    scatter_kernel<<<(N_EDGES + 255) / 256, 256>>>(src, dst, rid);

    // LayerNorms -> bf16 splits
    ln_split_kernel<<<N_NODES, 256>>>(ent, lne_g, lne_b, pxh, pxl);
    ln_split_kernel<<<N_REL, 256>>>(rel, lnr_g, lnr_b, prh, prl);

    // weight transposes + splits (head/tail/ent fused into one [768,256] buffer)
    dim3 tb(32, 8);
    trans_split_kernel<<<dim3(F_DIM / 32, F_DIM / 32), tb>>>(W_head, F_DIM, F_DIM,
                                                             pWph + 0 * F_DIM * F_DIM,
                                                             pWpl + 0 * F_DIM * F_DIM);
    trans_split_kernel<<<dim3(F_DIM / 32, F_DIM / 32), tb>>>(W_tail, F_DIM, F_DIM,
                                                             pWph + 1 * F_DIM * F_DIM,
                                                             pWpl + 1 * F_DIM * F_DIM);
    trans_split_kernel<<<dim3(F_DIM / 32, F_DIM / 32), tb>>>(W_ent,  F_DIM, F_DIM,
                                                             pWph + 2 * F_DIM * F_DIM,
                                                             pWpl + 2 * F_DIM * F_DIM);
    trans_split_kernel<<<dim3(F_DIM / 32, F_DIM / 32), tb>>>(W_rel,  F_DIM, F_DIM, pWrh, pWrl);
    trans_split_kernel<<<dim3(FF_DIM / 32, F_DIM / 32), tb>>>(W1, F_DIM, FF_DIM, pW1h, pW1l);
    trans_split_kernel<<<dim3(F_DIM / 32, FF_DIM / 32), tb>>>(W2, FF_DIM, F_DIM, pW2h, pW2l);

    // fused projection GEMM: [20000,256] @ [768,256]^T -> g_proj
    int mby = (N_NODES + 127) / 128;
    dim3 gP(PSTRIDE / 128, mby);
    gemm_mma_kernel<<<gP, 256, GEMM_SMEM>>>(pxh, pxl, pWph, pWpl, N_NODES, PSTRIDE, F_DIM,
                                            pproj, nullptr, nullptr, nullptr, nullptr, 0);
    dim3 gR(F_DIM / 128, 1);
    gemm_mma_kernel<<<gR, 256, GEMM_SMEM>>>(prh, prl, pWrh, pWrl, N_REL, F_DIM, F_DIM,
                                            pfr, nullptr, nullptr, nullptr, nullptr, 0);

    // attention + softmax
    attn_kernel<<<(N_NODES + 7) / 8, 256>>>(attnv);

    // 5 PPR hops (last fuses + ent_feat residual into rst)
    int nb = (N_NODES + 7) / 8;
    hop_kernel<<<nb, 256>>>(pproj + 512, PSTRIDE, pfeat, nullptr, 0);
    hop_kernel<<<nb, 256>>>(pfeat, F_DIM, pfeat2, nullptr, 0);
    hop_kernel<<<nb, 256>>>(pfeat2, F_DIM, pfeat, nullptr, 0);
    hop_kernel<<<nb, 256>>>(pfeat, F_DIM, pfeat2, nullptr, 0);
    hop_kernel<<<nb, 256>>>(pfeat2, F_DIM, prst, ent, 1);

    // FFN
    ln_split_kernel<<<N_NODES, 256>>>(prst, lnf_g, lnf_b, pyh, pyl);
    dim3 gH(FF_DIM / 128, mby);
    gemm_mma_kernel<<<gH, 256, GEMM_SMEM>>>(pyh, pyl, pW1h, pW1l, N_NODES, FF_DIM, F_DIM,
                                            nullptr, phh, phl, b1, nullptr, 1);
    dim3 gO(F_DIM / 128, mby);
    gemm_mma_kernel<<<gO, 256, GEMM_SMEM>>>(phh, phl, pW2h, pW2l, N_NODES, F_DIM, FF_DIM,
                                            out, nullptr, nullptr, b2, prst, 2);
}

// round 14
// speedup vs baseline: 1.2183x; 1.1377x over previous
#include <cuda_runtime.h>
#include <cuda_bf16.h>
#include <math.h>
#include <stdint.h>

#define N_NODES 20000
#define N_EDGES 320000
#define N_REL   100
#define F_DIM   256
#define FF_DIM  1024
#define H_HEADS 8
#define D_HEAD  32
#define SLOPE   0.2f
#define MAXD    128
#define PSTRIDE 768

// ======================= scratch (static device globals) =======================
__device__ __align__(16) float g_fh[N_NODES * F_DIM];
__device__ __align__(16) float g_ftl[N_NODES * F_DIM];
__device__ __align__(16) float g_fen[N_NODES * F_DIM];
__device__ __align__(16) float g_fr[N_REL * F_DIM];
__device__ int   g_deg[N_NODES];
__device__ int   g_cursor[N_NODES];
__device__ int   g_rowptr[N_NODES + 1];
__device__ float g_logdeg[N_NODES];
__device__ int   g_csr_src[N_EDGES];
__device__ int   g_csr_rid[N_EDGES];
__device__ __align__(16) float g_a[N_EDGES * H_HEADS];
__device__ __align__(16) float g_feat[N_NODES * F_DIM];
__device__ __align__(16) float g_feat2[N_NODES * F_DIM];
__device__ __align__(16) float g_rst[N_NODES * F_DIM];

// bf16 split activations
__device__ __align__(16) __nv_bfloat16 g_xh[N_NODES * F_DIM];
__device__ __align__(16) __nv_bfloat16 g_xl[N_NODES * F_DIM];
__device__ __align__(16) __nv_bfloat16 g_rh[N_REL * F_DIM];
__device__ __align__(16) __nv_bfloat16 g_rl[N_REL * F_DIM];
__device__ __align__(16) __nv_bfloat16 g_yh[N_NODES * F_DIM];
__device__ __align__(16) __nv_bfloat16 g_yl[N_NODES * F_DIM];
__device__ __align__(16) __nv_bfloat16 g_hidh[N_NODES * FF_DIM];
__device__ __align__(16) __nv_bfloat16 g_hidl[N_NODES * FF_DIM];

// bf16 split + transposed weights [N,K] K-major
__device__ __align__(16) __nv_bfloat16 g_Wph[3 * F_DIM * F_DIM], g_Wpl[3 * F_DIM * F_DIM];
__device__ __align__(16) __nv_bfloat16 g_Wrh[F_DIM * F_DIM], g_Wrl[F_DIM * F_DIM];
__device__ __align__(16) __nv_bfloat16 g_W1h[FF_DIM * F_DIM], g_W1l[FF_DIM * F_DIM];
__device__ __align__(16) __nv_bfloat16 g_W2h[F_DIM * FF_DIM], g_W2l[F_DIM * FF_DIM];

// ======================= CSR build =======================
__global__ void count_kernel(const int* __restrict__ dst) {
    int e = blockIdx.x * 256 + threadIdx.x;
    if (e < N_EDGES) atomicAdd(&g_deg[dst[e]], 1);
}
__global__ void scan_kernel() {
    __shared__ int sh[1024];
    __shared__ int carry_s;
    int t = threadIdx.x;
    if (t == 0) carry_s = 0;
    __syncthreads();
    for (int base = 0; base < N_NODES; base += 1024) {
        int i = base + t;
        int v = (i < N_NODES) ? g_deg[i] : 0;
        sh[t] = v;
        __syncthreads();
        for (int o = 1; o < 1024; o <<= 1) {
            int tmp = (t >= o) ? sh[t - o] : 0;
            __syncthreads();
            sh[t] += tmp;
            __syncthreads();
        }
        int incl = sh[t];
        if (i < N_NODES) {
            g_rowptr[i] = carry_s + incl - v;
            g_logdeg[i] = logf((float)v) * (1.0f / (float)D_HEAD);
        }
        __syncthreads();
        if (t == 1023) carry_s += incl;
        __syncthreads();
    }
    if (t == 0) g_rowptr[N_NODES] = N_EDGES;
}
__global__ void scatter_kernel(const int* __restrict__ src, const int* __restrict__ dst,
                               const int* __restrict__ rid) {
    int e = blockIdx.x * 256 + threadIdx.x;
    if (e < N_EDGES) {
        int d = dst[e];
        int p = g_rowptr[d] + atomicAdd(&g_cursor[d], 1);
        g_csr_src[p] = src[e];
        g_csr_rid[p] = rid[e];
    }
}

// ======================= LayerNorm -> bf16 hi/lo split (warp per row) =======================
__global__ void __launch_bounds__(256) ln_split_kernel(
    const float* __restrict__ in, const float* __restrict__ gg, const float* __restrict__ bb,
    __nv_bfloat16* __restrict__ oh, __nv_bfloat16* __restrict__ ol, int nrows) {
    int w = threadIdx.x >> 5, lane = threadIdx.x & 31;
    int row = blockIdx.x * 8 + w;
    if (row >= nrows) return;
    const float* x = in + (size_t)row * F_DIM + lane * 8;
    float4 v0 = *(const float4*)x;
    float4 v1 = *(const float4*)(x + 4);
    float vv[8] = {v0.x, v0.y, v0.z, v0.w, v1.x, v1.y, v1.z, v1.w};
    float s = 0.f, s2 = 0.f;
#pragma unroll
    for (int i = 0; i < 8; i++) { s += vv[i]; s2 += vv[i] * vv[i]; }
#pragma unroll
    for (int o = 16; o; o >>= 1) {
        s  += __shfl_xor_sync(0xFFFFFFFFu, s, o);
        s2 += __shfl_xor_sync(0xFFFFFFFFu, s2, o);
    }
    float mean = s * (1.0f / F_DIM);
    float var = s2 * (1.0f / F_DIM) - mean * mean;
    float inv = rsqrtf(var + 1e-5f);
    float4 gg0 = *(const float4*)(gg + lane * 8);
    float4 gg1 = *(const float4*)(gg + lane * 8 + 4);
    float4 bb0 = *(const float4*)(bb + lane * 8);
    float4 bb1 = *(const float4*)(bb + lane * 8 + 4);
    float gv[8] = {gg0.x, gg0.y, gg0.z, gg0.w, gg1.x, gg1.y, gg1.z, gg1.w};
    float bv[8] = {bb0.x, bb0.y, bb0.z, bb0.w, bb1.x, bb1.y, bb1.z, bb1.w};
    __nv_bfloat16 hh[8], ll[8];
#pragma unroll
    for (int i = 0; i < 8; i++) {
        float r = (vv[i] - mean) * inv * gv[i] + bv[i];
        hh[i] = __float2bfloat16(r);
        ll[i] = __float2bfloat16(r - __bfloat162float(hh[i]));
    }
    size_t idx = (size_t)row * F_DIM + lane * 8;
    *(uint4*)(oh + idx) = *(uint4*)hh;
    *(uint4*)(ol + idx) = *(uint4*)ll;
}

// ======================= weight transpose + split: W[K,N] -> Wt[N,K] bf16 hi/lo =======================
__global__ void trans_split_kernel(const float* __restrict__ W, int K, int Nc,
                                   __nv_bfloat16* __restrict__ Th, __nv_bfloat16* __restrict__ Tl) {
    __shared__ float t[32][33];
    int n0 = blockIdx.x * 32, k0 = blockIdx.y * 32;
    int tx = threadIdx.x, ty = threadIdx.y;  // 32 x 8
#pragma unroll
    for (int j = 0; j < 32; j += 8)
        t[ty + j][tx] = W[(size_t)(k0 + ty + j) * Nc + n0 + tx];
    __syncthreads();
#pragma unroll
    for (int j = 0; j < 32; j += 8) {
        float v = t[tx][ty + j];
        int n = n0 + ty + j, k = k0 + tx;
        __nv_bfloat16 h = __float2bfloat16(v);
        Th[(size_t)n * K + k] = h;
        Tl[(size_t)n * K + k] = __float2bfloat16(v - __bfloat162float(h));
    }
}

// ======================= HMMA GEMM (cp.async double-buffered, 128x128 tile) =======================
// modes: 0: C=fp32 stride Nc. 1: +bias,relu -> Ch/Cl bf16. 2: +bias+resid -> fp32.
//        3: split3 compact fp32 (col block 0->Cf, 1->Cf2, 2->Cf3, stride 256)

#define KC 32
#define LDT 40
#define TSZ (128 * LDT)
#define STG (4 * TSZ)
#define GEMM_SMEM (2 * STG * 2)

__device__ __forceinline__ void mma16816(float* c, uint32_t a0, uint32_t a1, uint32_t a2,
                                         uint32_t a3, uint32_t b0, uint32_t b1) {
    asm volatile(
        "mma.sync.aligned.m16n8k16.row.col.f32.bf16.bf16.f32 "
        "{%0,%1,%2,%3}, {%4,%5,%6,%7}, {%8,%9}, {%0,%1,%2,%3};"
        : "+f"(c[0]), "+f"(c[1]), "+f"(c[2]), "+f"(c[3])
        : "r"(a0), "r"(a1), "r"(a2), "r"(a3), "r"(b0), "r"(b1));
}

__device__ __forceinline__ void cp_async16(uint32_t saddr, const void* gptr) {
    asm volatile("cp.async.cg.shared.global [%0], [%1], 16;" :: "r"(saddr), "l"(gptr));
}
#define CP_COMMIT() asm volatile("cp.async.commit_group;" ::: "memory")
#define CP_WAIT0()  asm volatile("cp.async.wait_group 0;" ::: "memory")
#define CP_WAIT1()  asm volatile("cp.async.wait_group 1;" ::: "memory")

__global__ void __launch_bounds__(256, 2) gemm_mma_kernel(
    const __nv_bfloat16* __restrict__ Ah, const __nv_bfloat16* __restrict__ Al,
    const __nv_bfloat16* __restrict__ Bh, const __nv_bfloat16* __restrict__ Bl,
    int M, int Nc, int K,
    float* __restrict__ Cf, float* __restrict__ Cf2, float* __restrict__ Cf3,
    __nv_bfloat16* __restrict__ Ch, __nv_bfloat16* __restrict__ Cl,
    const float* __restrict__ bias, const float* __restrict__ resid, int mode) {
    extern __shared__ __nv_bfloat16 smp[];
    uint32_t sbase;
    asm("{ .reg .u64 t; cvta.to.shared.u64 t, %1; cvt.u32.u64 %0, t; }"
        : "=r"(sbase) : "l"(smp));

    const int tid = threadIdx.x;
    const int wid = tid >> 5, lane = tid & 31;
    const int g = lane >> 2, tig = lane & 3;
    const int wm = (wid >> 1) * 32;
    const int wn = (wid & 1) * 64;
    const int bm = blockIdx.y * 128, bn = blockIdx.x * 128;

    int s_row[2], s_c8[2];
    size_t aoff0[2], boff0[2];
#pragma unroll
    for (int half = 0; half < 2; half++) {
        int idx = half * 256 + tid;
        int row = idx >> 2;
        int c8 = (idx & 3) * 8;
        s_row[half] = row;
        s_c8[half] = c8;
        int gra = bm + row; if (gra > M - 1) gra = M - 1;
        int grb = bn + row; if (grb > Nc - 1) grb = Nc - 1;
        aoff0[half] = (size_t)gra * K + c8;
        boff0[half] = (size_t)grb * K + c8;
    }

    float acc[2][8][4];
#pragma unroll
    for (int i = 0; i < 2; i++)
#pragma unroll
        for (int j = 0; j < 8; j++)
#pragma unroll
            for (int k = 0; k < 4; k++) acc[i][j][k] = 0.f;

    const int nchunk = K / KC;

#pragma unroll
    for (int half = 0; half < 2; half++) {
        uint32_t so = sbase + (uint32_t)(s_row[half] * LDT + s_c8[half]) * 2;
        cp_async16(so + 0 * TSZ * 2, Ah + aoff0[half]);
        cp_async16(so + 1 * TSZ * 2, Al + aoff0[half]);
        cp_async16(so + 2 * TSZ * 2, Bh + boff0[half]);
        cp_async16(so + 3 * TSZ * 2, Bl + boff0[half]);
    }
    CP_COMMIT();

    for (int c = 0; c < nchunk; c++) {
        if (c + 1 < nchunk) {
            int kb = (c + 1) * KC;
            uint32_t stb = sbase + (uint32_t)(((c + 1) & 1) * STG) * 2;
#pragma unroll
            for (int half = 0; half < 2; half++) {
                uint32_t so = stb + (uint32_t)(s_row[half] * LDT + s_c8[half]) * 2;
                cp_async16(so + 0 * TSZ * 2, Ah + aoff0[half] + kb);
                cp_async16(so + 1 * TSZ * 2, Al + aoff0[half] + kb);
                cp_async16(so + 2 * TSZ * 2, Bh + boff0[half] + kb);
                cp_async16(so + 3 * TSZ * 2, Bl + boff0[half] + kb);
            }
            CP_COMMIT();
            CP_WAIT1();
        } else {
            CP_WAIT0();
        }
        __syncthreads();

        const __nv_bfloat16* sAh = smp + (c & 1) * STG;
        const __nv_bfloat16* sAl = sAh + TSZ;
        const __nv_bfloat16* sBh = sAh + 2 * TSZ;
        const __nv_bfloat16* sBl = sAh + 3 * TSZ;

#pragma unroll
        for (int ks = 0; ks < 2; ks++) {
            const int kk = ks * 16 + tig * 2;
            uint32_t ah[2][4], al[2][4];
#pragma unroll
            for (int mt = 0; mt < 2; mt++) {
                int r0 = (wm + mt * 16 + g) * LDT;
                int r1 = r0 + 8 * LDT;
                ah[mt][0] = *(const uint32_t*)&sAh[r0 + kk];
                ah[mt][1] = *(const uint32_t*)&sAh[r1 + kk];
                ah[mt][2] = *(const uint32_t*)&sAh[r0 + kk + 8];
                ah[mt][3] = *(const uint32_t*)&sAh[r1 + kk + 8];
                al[mt][0] = *(const uint32_t*)&sAl[r0 + kk];
                al[mt][1] = *(const uint32_t*)&sAl[r1 + kk];
                al[mt][2] = *(const uint32_t*)&sAl[r0 + kk + 8];
                al[mt][3] = *(const uint32_t*)&sAl[r1 + kk + 8];
            }
#pragma unroll
            for (int nt = 0; nt < 8; nt++) {
                int nrow = (wn + nt * 8 + g) * LDT;
                uint32_t bh0 = *(const uint32_t*)&sBh[nrow + kk];
                uint32_t bh1 = *(const uint32_t*)&sBh[nrow + kk + 8];
                uint32_t bl0 = *(const uint32_t*)&sBl[nrow + kk];
                uint32_t bl1 = *(const uint32_t*)&sBl[nrow + kk + 8];
#pragma unroll
                for (int mt = 0; mt < 2; mt++) {
                    mma16816(acc[mt][nt], ah[mt][0], ah[mt][1], ah[mt][2], ah[mt][3], bh0, bh1);
                    mma16816(acc[mt][nt], ah[mt][0], ah[mt][1], ah[mt][2], ah[mt][3], bl0, bl1);
                    mma16816(acc[mt][nt], al[mt][0], al[mt][1], al[mt][2], al[mt][3], bh0, bh1);
                }
            }
        }
        __syncthreads();
    }

    // ---- epilogue ----
#pragma unroll
    for (int mt = 0; mt < 2; mt++) {
        int row0 = bm + wm + mt * 16 + g;
        int row1 = row0 + 8;
#pragma unroll
        for (int nt = 0; nt < 8; nt++) {
            int col = bn + wn + nt * 8 + tig * 2;
#pragma unroll
            for (int half = 0; half < 2; half++) {
                int row = half ? row1 : row0;
                if (row >= M) continue;
                float v0 = acc[mt][nt][half * 2 + 0];
                float v1 = acc[mt][nt][half * 2 + 1];
                if (mode == 0) {
                    size_t idx = (size_t)row * Nc + col;
                    Cf[idx] = v0; Cf[idx + 1] = v1;
                } else if (mode == 3) {
                    int blk = col >> 8, c2 = col & 255;
                    float* dstp = (blk == 0) ? Cf : ((blk == 1) ? Cf2 : Cf3);
                    size_t idx = (size_t)row * 256 + c2;
                    dstp[idx] = v0; dstp[idx + 1] = v1;
                } else if (mode == 1) {
                    size_t idx = (size_t)row * Nc + col;
                    v0 = fmaxf(v0 + bias[col], 0.f);
                    v1 = fmaxf(v1 + bias[col + 1], 0.f);
                    __nv_bfloat16 h0 = __float2bfloat16(v0);
                    __nv_bfloat16 h1 = __float2bfloat16(v1);
                    Ch[idx] = h0; Ch[idx + 1] = h1;
                    Cl[idx] = __float2bfloat16(v0 - __bfloat162float(h0));
                    Cl[idx + 1] = __float2bfloat16(v1 - __bfloat162float(h1));
                } else {
                    size_t idx = (size_t)row * Nc + col;
                    Cf[idx] = v0 + bias[col] + resid[idx];
                    Cf[idx + 1] = v1 + bias[col + 1] + resid[idx + 1];
                }
            }
        }
    }
}

// ======================= edge attention + softmax (warp per dst node) =======================
__global__ void __launch_bounds__(256) attn_kernel(const float* __restrict__ attnv) {
    __shared__ float sh_e[8][MAXD][8];
    int w = threadIdx.x >> 5;
    int lane = threadIdx.x & 31;
    int v = blockIdx.x * 8 + w;
    if (v >= N_NODES) return;

    float ftl_v[8], at[8];
#pragma unroll
    for (int h = 0; h < 8; h++) {
        ftl_v[h] = g_ftl[(size_t)v * F_DIM + h * 32 + lane];
        at[h] = attnv[h * 32 + lane];
    }
    float ld = g_logdeg[v];
    int s0 = g_rowptr[v], s1 = g_rowptr[v + 1];
    int cnt = s1 - s0;
    int cc = cnt < MAXD ? cnt : MAXD;

    float m8[8];
#pragma unroll
    for (int h = 0; h < 8; h++) m8[h] = -1e30f;

    for (int q = 0; q < cc; q++) {
        int p = s0 + q;
        int s = g_csr_src[p], rr = g_csr_rid[p];
        const float* fhp = &g_fh[(size_t)s * F_DIM + lane];
        const float* frp = &g_fr[(size_t)rr * F_DIM + lane];
#pragma unroll
        for (int h = 0; h < 8; h++) {
            float x = __ldg(fhp + h * 32) * ftl_v[h] * __ldg(frp + h * 32);
            x = x > 0.f ? x : SLOPE * x;
            float e = x * at[h];
#pragma unroll
            for (int o = 16; o; o >>= 1) e += __shfl_xor_sync(0xFFFFFFFFu, e, o);
            e *= ld;
            m8[h] = fmaxf(m8[h], e);
            if (lane == h) sh_e[w][q][h] = e;
        }
    }
    __syncwarp();

    float s8[8];
#pragma unroll
    for (int h = 0; h < 8; h++) s8[h] = 0.f;
    for (int q = lane; q < cc; q += 32) {
#pragma unroll
        for (int h = 0; h < 8; h++) {
            float ex = expf(sh_e[w][q][h] - m8[h]);
            sh_e[w][q][h] = ex;
            s8[h] += ex;
        }
    }
#pragma unroll
    for (int h = 0; h < 8; h++) {
        float t = s8[h];
#pragma unroll
        for (int o = 16; o; o >>= 1) t += __shfl_xor_sync(0xFFFFFFFFu, t, o);
        s8[h] = 1.0f / t;
    }
    __syncwarp();
    for (int q = lane; q < cc; q += 32) {
        int p = s0 + q;
        float4 o0, o1;
        o0.x = sh_e[w][q][0] * s8[0]; o0.y = sh_e[w][q][1] * s8[1];
        o0.z = sh_e[w][q][2] * s8[2]; o0.w = sh_e[w][q][3] * s8[3];
        o1.x = sh_e[w][q][4] * s8[4]; o1.y = sh_e[w][q][5] * s8[5];
        o1.z = sh_e[w][q][6] * s8[6]; o1.w = sh_e[w][q][7] * s8[7];
        *(float4*)&g_a[(size_t)p * 8] = o0;
        *(float4*)&g_a[(size_t)p * 8 + 4] = o1;
    }
}

// ======================= PPR hop (warp per dst node; atomic-free via CSR) =======================
__global__ void __launch_bounds__(256) hop_kernel(const float* __restrict__ fin,
                                                  float* __restrict__ fout,
                                                  const float* __restrict__ ent, int addent) {
    int w = threadIdx.x >> 5, lane = threadIdx.x & 31;
    int v = blockIdx.x * 8 + w;
    if (v >= N_NODES) return;
    int s0 = g_rowptr[v], s1 = g_rowptr[v + 1];
    float acc[8] = {0.f, 0.f, 0.f, 0.f, 0.f, 0.f, 0.f, 0.f};
    for (int p = s0; p < s1; p++) {
        int s = g_csr_src[p];
        const float4* ap = (const float4*)&g_a[(size_t)p * 8];
        float4 a0 = __ldg(ap), a1 = __ldg(ap + 1);
        const float* f = fin + (size_t)s * F_DIM + lane;
        acc[0] += __ldg(f)       * a0.x; acc[1] += __ldg(f + 32)  * a0.y;
        acc[2] += __ldg(f + 64)  * a0.z; acc[3] += __ldg(f + 96)  * a0.w;
        acc[4] += __ldg(f + 128) * a1.x; acc[5] += __ldg(f + 160) * a1.y;
        acc[6] += __ldg(f + 192) * a1.z; acc[7] += __ldg(f + 224) * a1.w;
    }
    size_t base = (size_t)v * F_DIM + lane;
#pragma unroll
    for (int h = 0; h < 8; h++) {
        float r = 0.9f * acc[h] + 0.1f * g_fen[base + h * 32];
        if (addent) r += ent[base + h * 32];
        fout[base + h * 32] = r;
    }
}

// ======================= launch =======================
extern "C" void kernel_launch(void* const* d_in, const int* in_sizes, int n_in,
                              void* d_out, int out_size) {
    const float* ent    = (const float*)d_in[0];
    const float* rel    = (const float*)d_in[1];
    const float* W_head = (const float*)d_in[2];
    const float* W_tail = (const float*)d_in[3];
    const float* W_ent  = (const float*)d_in[4];
    const float* W_rel  = (const float*)d_in[5];
    const float* attnv  = (const float*)d_in[6];
    const float* lne_g = (const float*)d_in[7];
    const float* lne_b = (const float*)d_in[8];
    const float* lnr_g = (const float*)d_in[9];
    const float* lnr_b = (const float*)d_in[10];
    const float* lnf_g = (const float*)d_in[11];
    const float* lnf_b = (const float*)d_in[12];
    const float* W1 = (const float*)d_in[13];
    const float* b1 = (const float*)d_in[14];
    const float* W2 = (const float*)d_in[15];
    const float* b2 = (const float*)d_in[16];
    const int* src = (const int*)d_in[17];
    const int* dst = (const int*)d_in[18];
    const int* rid = (const int*)d_in[19];
    float* out = (float*)d_out;

    float *pfh, *pftl, *pfen, *pfr, *pfeat, *pfeat2, *prst;
    cudaGetSymbolAddress((void**)&pfh, g_fh);
    cudaGetSymbolAddress((void**)&pftl, g_ftl);
    cudaGetSymbolAddress((void**)&pfen, g_fen);
    cudaGetSymbolAddress((void**)&pfr, g_fr);
    cudaGetSymbolAddress((void**)&pfeat, g_feat);
    cudaGetSymbolAddress((void**)&pfeat2, g_feat2);
    cudaGetSymbolAddress((void**)&prst, g_rst);

    int *pdeg, *pcursor;
    cudaGetSymbolAddress((void**)&pdeg, g_deg);
    cudaGetSymbolAddress((void**)&pcursor, g_cursor);

    __nv_bfloat16 *pxh, *pxl, *prh, *prl, *pyh, *pyl, *phh, *phl;
    cudaGetSymbolAddress((void**)&pxh, g_xh);
    cudaGetSymbolAddress((void**)&pxl, g_xl);
    cudaGetSymbolAddress((void**)&prh, g_rh);
    cudaGetSymbolAddress((void**)&prl, g_rl);
    cudaGetSymbolAddress((void**)&pyh, g_yh);
    cudaGetSymbolAddress((void**)&pyl, g_yl);
    cudaGetSymbolAddress((void**)&phh, g_hidh);
    cudaGetSymbolAddress((void**)&phl, g_hidl);

    __nv_bfloat16 *pWph, *pWpl, *pWrh, *pWrl, *pW1h, *pW1l, *pW2h, *pW2l;
    cudaGetSymbolAddress((void**)&pWph, g_Wph); cudaGetSymbolAddress((void**)&pWpl, g_Wpl);
    cudaGetSymbolAddress((void**)&pWrh, g_Wrh); cudaGetSymbolAddress((void**)&pWrl, g_Wrl);
    cudaGetSymbolAddress((void**)&pW1h, g_W1h); cudaGetSymbolAddress((void**)&pW1l, g_W1l);
    cudaGetSymbolAddress((void**)&pW2h, g_W2h); cudaGetSymbolAddress((void**)&pW2l, g_W2l);

    cudaFuncSetAttribute(gemm_mma_kernel, cudaFuncAttributeMaxDynamicSharedMemorySize, GEMM_SMEM);

    // streams/events for preamble overlap (created once; no device allocations)
    static cudaStream_t s1 = nullptr, s2 = nullptr;
    static cudaEvent_t e_fork = nullptr, e_j1 = nullptr, e_j2 = nullptr;
    if (s1 == nullptr) {
        cudaStreamCreateWithFlags(&s1, cudaStreamNonBlocking);
        cudaStreamCreateWithFlags(&s2, cudaStreamNonBlocking);
        cudaEventCreateWithFlags(&e_fork, cudaEventDisableTiming);
        cudaEventCreateWithFlags(&e_j1, cudaEventDisableTiming);
        cudaEventCreateWithFlags(&e_j2, cudaEventDisableTiming);
    }

    // fork side streams off the capture (legacy) stream
    cudaEventRecord(e_fork, 0);
    cudaStreamWaitEvent(s1, e_fork, 0);
    cudaStreamWaitEvent(s2, e_fork, 0);

    // ---- s1: CSR build ----
    cudaMemsetAsync(pdeg, 0, N_NODES * sizeof(int), s1);
    cudaMemsetAsync(pcursor, 0, N_NODES * sizeof(int), s1);
    count_kernel<<<(N_EDGES + 255) / 256, 256, 0, s1>>>(dst);
    scan_kernel<<<1, 1024, 0, s1>>>();
    scatter_kernel<<<(N_EDGES + 255) / 256, 256, 0, s1>>>(src, dst, rid);
    cudaEventRecord(e_j1, s1);

    // ---- s2: rel path + FFN weight transposes ----
    dim3 tb(32, 8);
    ln_split_kernel<<<(N_REL + 7) / 8, 256, 0, s2>>>(rel, lnr_g, lnr_b, prh, prl, N_REL);
    trans_split_kernel<<<dim3(F_DIM / 32, F_DIM / 32), tb, 0, s2>>>(W_rel, F_DIM, F_DIM, pWrh, pWrl);
    gemm_mma_kernel<<<dim3(F_DIM / 128, 1), 256, GEMM_SMEM, s2>>>(
        prh, prl, pWrh, pWrl, N_REL, F_DIM, F_DIM,
        pfr, nullptr, nullptr, nullptr, nullptr, nullptr, nullptr, 0);
    trans_split_kernel<<<dim3(FF_DIM / 32, F_DIM / 32), tb, 0, s2>>>(W1, F_DIM, FF_DIM, pW1h, pW1l);
    trans_split_kernel<<<dim3(F_DIM / 32, FF_DIM / 32), tb, 0, s2>>>(W2, FF_DIM, F_DIM, pW2h, pW2l);
    cudaEventRecord(e_j2, s2);

    // ---- main stream: ent LN + proj transposes + fused proj GEMM ----
    ln_split_kernel<<<(N_NODES + 7) / 8, 256>>>(ent, lne_g, lne_b, pxh, pxl, N_NODES);
    trans_split_kernel<<<dim3(F_DIM / 32, F_DIM / 32), tb>>>(W_head, F_DIM, F_DIM,
                                                             pWph + 0 * F_DIM * F_DIM,
                                                             pWpl + 0 * F_DIM * F_DIM);
    trans_split_kernel<<<dim3(F_DIM / 32, F_DIM / 32), tb>>>(W_tail, F_DIM, F_DIM,
                                                             pWph + 1 * F_DIM * F_DIM,
                                                             pWpl + 1 * F_DIM * F_DIM);
    trans_split_kernel<<<dim3(F_DIM / 32, F_DIM / 32), tb>>>(W_ent,  F_DIM, F_DIM,
                                                             pWph + 2 * F_DIM * F_DIM,
                                                             pWpl + 2 * F_DIM * F_DIM);
    int mby = (N_NODES + 127) / 128;
    gemm_mma_kernel<<<dim3(PSTRIDE / 128, mby), 256, GEMM_SMEM>>>(
        pxh, pxl, pWph, pWpl, N_NODES, PSTRIDE, F_DIM,
        pfh, pftl, pfen, nullptr, nullptr, nullptr, nullptr, 3);

    // join side streams before attention
    cudaStreamWaitEvent(0, e_j1, 0);
    cudaStreamWaitEvent(0, e_j2, 0);

    // attention + softmax
    attn_kernel<<<(N_NODES + 7) / 8, 256>>>(attnv);

    // 5 PPR hops (last fuses + ent_feat residual into rst)
    int nb = (N_NODES + 7) / 8;
    hop_kernel<<<nb, 256>>>(pfen, pfeat, nullptr, 0);
    hop_kernel<<<nb, 256>>>(pfeat, pfeat2, nullptr, 0);
    hop_kernel<<<nb, 256>>>(pfeat2, pfeat, nullptr, 0);
    hop_kernel<<<nb, 256>>>(pfeat, pfeat2, nullptr, 0);
    hop_kernel<<<nb, 256>>>(pfeat2, prst, ent, 1);

    // FFN
    ln_split_kernel<<<(N_NODES + 7) / 8, 256>>>(prst, lnf_g, lnf_b, pyh, pyl, N_NODES);
    gemm_mma_kernel<<<dim3(FF_DIM / 128, mby), 256, GEMM_SMEM>>>(
        pyh, pyl, pW1h, pW1l, N_NODES, FF_DIM, F_DIM,
        nullptr, nullptr, nullptr, phh, phl, b1, nullptr, 1);
    gemm_mma_kernel<<<dim3(F_DIM / 128, mby), 256, GEMM_SMEM>>>(
        phh, phl, pW2h, pW2l, N_NODES, F_DIM, FF_DIM,
        out, nullptr, nullptr, nullptr, nullptr, b2, prst, 2);
}

// round 16
// speedup vs baseline: 1.2186x; 1.0003x over previous
#include <cuda_runtime.h>
#include <cuda_bf16.h>
#include <math.h>
#include <stdint.h>

#define N_NODES 20000
#define N_EDGES 320000
#define N_REL   100
#define F_DIM   256
#define FF_DIM  1024
#define H_HEADS 8
#define D_HEAD  32
#define SLOPE   0.2f
#define MAXD    128

// ======================= scratch (static device globals) =======================
__device__ __align__(16) float g_fh[N_NODES * F_DIM];
__device__ __align__(16) float g_ftl[N_NODES * F_DIM];
__device__ __align__(16) float g_fen[N_NODES * F_DIM];
__device__ __align__(16) float g_fr[N_REL * F_DIM];
__device__ int   g_deg[N_NODES];
__device__ int   g_cursor[N_NODES];
__device__ int   g_rowptr[N_NODES + 1];
__device__ float g_logdeg[N_NODES];
__device__ int   g_csr_src[N_EDGES];
__device__ int   g_csr_rid[N_EDGES];
__device__ __align__(16) float g_a[N_EDGES * H_HEADS];
__device__ __align__(16) float g_feat[N_NODES * F_DIM];
__device__ __align__(16) float g_feat2[N_NODES * F_DIM];
__device__ __align__(16) float g_rst[N_NODES * F_DIM];

// bf16 split activations
__device__ __align__(16) __nv_bfloat16 g_xh[N_NODES * F_DIM];
__device__ __align__(16) __nv_bfloat16 g_xl[N_NODES * F_DIM];
__device__ __align__(16) __nv_bfloat16 g_rh[N_REL * F_DIM];
__device__ __align__(16) __nv_bfloat16 g_rl[N_REL * F_DIM];
__device__ __align__(16) __nv_bfloat16 g_yh[N_NODES * F_DIM];
__device__ __align__(16) __nv_bfloat16 g_yl[N_NODES * F_DIM];
__device__ __align__(16) __nv_bfloat16 g_hidh[N_NODES * FF_DIM];
__device__ __align__(16) __nv_bfloat16 g_hidl[N_NODES * FF_DIM];

// bf16 split + transposed weights [N,K] K-major
__device__ __align__(16) __nv_bfloat16 g_Wph[3 * F_DIM * F_DIM], g_Wpl[3 * F_DIM * F_DIM];
__device__ __align__(16) __nv_bfloat16 g_Wrh[F_DIM * F_DIM], g_Wrl[F_DIM * F_DIM];
__device__ __align__(16) __nv_bfloat16 g_W1h[FF_DIM * F_DIM], g_W1l[FF_DIM * F_DIM];
__device__ __align__(16) __nv_bfloat16 g_W2h[F_DIM * FF_DIM], g_W2l[F_DIM * FF_DIM];

// ======================= CSR build =======================
__global__ void count_kernel(const int* __restrict__ dst) {
    int e = blockIdx.x * 256 + threadIdx.x;
    if (e < N_EDGES) atomicAdd(&g_deg[dst[e]], 1);
}
__global__ void scan_kernel() {
    __shared__ int sh[1024];
    __shared__ int carry_s;
    int t = threadIdx.x;
    if (t == 0) carry_s = 0;
    __syncthreads();
    for (int base = 0; base < N_NODES; base += 1024) {
        int i = base + t;
        int v = (i < N_NODES) ? g_deg[i] : 0;
        sh[t] = v;
        __syncthreads();
        for (int o = 1; o < 1024; o <<= 1) {
            int tmp = (t >= o) ? sh[t - o] : 0;
            __syncthreads();
            sh[t] += tmp;
            __syncthreads();
        }
        int incl = sh[t];
        if (i < N_NODES) {
            g_rowptr[i] = carry_s + incl - v;
            g_logdeg[i] = logf((float)v) * (1.0f / (float)D_HEAD);
        }
        __syncthreads();
        if (t == 1023) carry_s += incl;
        __syncthreads();
    }
    if (t == 0) g_rowptr[N_NODES] = N_EDGES;
}
__global__ void scatter_kernel(const int* __restrict__ src, const int* __restrict__ dst,
                               const int* __restrict__ rid) {
    int e = blockIdx.x * 256 + threadIdx.x;
    if (e < N_EDGES) {
        int d = dst[e];
        int p = g_rowptr[d] + atomicAdd(&g_cursor[d], 1);
        g_csr_src[p] = src[e];
        g_csr_rid[p] = rid[e];
    }
}

// ======================= LayerNorm -> bf16 hi/lo split (warp per row) =======================
__global__ void __launch_bounds__(256) ln_split_kernel(
    const float* __restrict__ in, const float* __restrict__ gg, const float* __restrict__ bb,
    __nv_bfloat16* __restrict__ oh, __nv_bfloat16* __restrict__ ol, int nrows) {
    int w = threadIdx.x >> 5, lane = threadIdx.x & 31;
    int row = blockIdx.x * 8 + w;
    if (row >= nrows) return;
    const float* x = in + (size_t)row * F_DIM + lane * 8;
    float4 v0 = *(const float4*)x;
    float4 v1 = *(const float4*)(x + 4);
    float vv[8] = {v0.x, v0.y, v0.z, v0.w, v1.x, v1.y, v1.z, v1.w};
    float s = 0.f, s2 = 0.f;
#pragma unroll
    for (int i = 0; i < 8; i++) { s += vv[i]; s2 += vv[i] * vv[i]; }
#pragma unroll
    for (int o = 16; o; o >>= 1) {
        s  += __shfl_xor_sync(0xFFFFFFFFu, s, o);
        s2 += __shfl_xor_sync(0xFFFFFFFFu, s2, o);
    }
    float mean = s * (1.0f / F_DIM);
    float var = s2 * (1.0f / F_DIM) - mean * mean;
    float inv = rsqrtf(var + 1e-5f);
    float4 gg0 = *(const float4*)(gg + lane * 8);
    float4 gg1 = *(const float4*)(gg + lane * 8 + 4);
    float4 bb0 = *(const float4*)(bb + lane * 8);
    float4 bb1 = *(const float4*)(bb + lane * 8 + 4);
    float gv[8] = {gg0.x, gg0.y, gg0.z, gg0.w, gg1.x, gg1.y, gg1.z, gg1.w};
    float bv[8] = {bb0.x, bb0.y, bb0.z, bb0.w, bb1.x, bb1.y, bb1.z, bb1.w};
    __nv_bfloat16 hh[8], ll[8];
#pragma unroll
    for (int i = 0; i < 8; i++) {
        float r = (vv[i] - mean) * inv * gv[i] + bv[i];
        hh[i] = __float2bfloat16(r);
        ll[i] = __float2bfloat16(r - __bfloat162float(hh[i]));
    }
    size_t idx = (size_t)row * F_DIM + lane * 8;
    *(uint4*)(oh + idx) = *(uint4*)hh;
    *(uint4*)(ol + idx) = *(uint4*)ll;
}

// ======================= weight transpose + split: W[K,N] -> Wt[N,K] bf16 hi/lo =======================
__global__ void trans_split_kernel(const float* __restrict__ W, int K, int Nc,
                                   __nv_bfloat16* __restrict__ Th, __nv_bfloat16* __restrict__ Tl) {
    __shared__ float t[32][33];
    int n0 = blockIdx.x * 32, k0 = blockIdx.y * 32;
    int tx = threadIdx.x, ty = threadIdx.y;  // 32 x 8
#pragma unroll
    for (int j = 0; j < 32; j += 8)
        t[ty + j][tx] = W[(size_t)(k0 + ty + j) * Nc + n0 + tx];
    __syncthreads();
#pragma unroll
    for (int j = 0; j < 32; j += 8) {
        float v = t[tx][ty + j];
        int n = n0 + ty + j, k = k0 + tx;
        __nv_bfloat16 h = __float2bfloat16(v);
        Th[(size_t)n * K + k] = h;
        Tl[(size_t)n * K + k] = __float2bfloat16(v - __bfloat162float(h));
    }
}

// ======================= HMMA GEMM (cp.async double-buffered, 128x128 tile) =======================
// modes: 0: C=fp32 stride Nc. 1: +bias,relu -> Ch/Cl bf16. 2: +bias+resid -> fp32.
//        3: split compact fp32 (col block 0->Cf, 1->Cf2, 2->Cf3, stride 256)

#define KC 32
#define LDT 40
#define TSZ (128 * LDT)
#define STG (4 * TSZ)
#define GEMM_SMEM (2 * STG * 2)

__device__ __forceinline__ void mma16816(float* c, uint32_t a0, uint32_t a1, uint32_t a2,
                                         uint32_t a3, uint32_t b0, uint32_t b1) {
    asm volatile(
        "mma.sync.aligned.m16n8k16.row.col.f32.bf16.bf16.f32 "
        "{%0,%1,%2,%3}, {%4,%5,%6,%7}, {%8,%9}, {%0,%1,%2,%3};"
        : "+f"(c[0]), "+f"(c[1]), "+f"(c[2]), "+f"(c[3])
        : "r"(a0), "r"(a1), "r"(a2), "r"(a3), "r"(b0), "r"(b1));
}

__device__ __forceinline__ void cp_async16(uint32_t saddr, const void* gptr) {
    asm volatile("cp.async.cg.shared.global [%0], [%1], 16;" :: "r"(saddr), "l"(gptr));
}
#define CP_COMMIT() asm volatile("cp.async.commit_group;" ::: "memory")
#define CP_WAIT0()  asm volatile("cp.async.wait_group 0;" ::: "memory")
#define CP_WAIT1()  asm volatile("cp.async.wait_group 1;" ::: "memory")

__global__ void __launch_bounds__(256, 2) gemm_mma_kernel(
    const __nv_bfloat16* __restrict__ Ah, const __nv_bfloat16* __restrict__ Al,
    const __nv_bfloat16* __restrict__ Bh, const __nv_bfloat16* __restrict__ Bl,
    int M, int Nc, int K,
    float* __restrict__ Cf, float* __restrict__ Cf2, float* __restrict__ Cf3,
    __nv_bfloat16* __restrict__ Ch, __nv_bfloat16* __restrict__ Cl,
    const float* __restrict__ bias, const float* __restrict__ resid, int mode) {
    extern __shared__ __nv_bfloat16 smp[];
    uint32_t sbase;
    asm("{ .reg .u64 t; cvta.to.shared.u64 t, %1; cvt.u32.u64 %0, t; }"
        : "=r"(sbase) : "l"(smp));

    const int tid = threadIdx.x;
    const int wid = tid >> 5, lane = tid & 31;
    const int g = lane >> 2, tig = lane & 3;
    const int wm = (wid >> 1) * 32;
    const int wn = (wid & 1) * 64;
    const int bm = blockIdx.y * 128, bn = blockIdx.x * 128;

    int s_row[2], s_c8[2];
    size_t aoff0[2], boff0[2];
#pragma unroll
    for (int half = 0; half < 2; half++) {
        int idx = half * 256 + tid;
        int row = idx >> 2;
        int c8 = (idx & 3) * 8;
        s_row[half] = row;
        s_c8[half] = c8;
        int gra = bm + row; if (gra > M - 1) gra = M - 1;
        int grb = bn + row; if (grb > Nc - 1) grb = Nc - 1;
        aoff0[half] = (size_t)gra * K + c8;
        boff0[half] = (size_t)grb * K + c8;
    }

    float acc[2][8][4];
#pragma unroll
    for (int i = 0; i < 2; i++)
#pragma unroll
        for (int j = 0; j < 8; j++)
#pragma unroll
            for (int k = 0; k < 4; k++) acc[i][j][k] = 0.f;

    const int nchunk = K / KC;

#pragma unroll
    for (int half = 0; half < 2; half++) {
        uint32_t so = sbase + (uint32_t)(s_row[half] * LDT + s_c8[half]) * 2;
        cp_async16(so + 0 * TSZ * 2, Ah + aoff0[half]);
        cp_async16(so + 1 * TSZ * 2, Al + aoff0[half]);
        cp_async16(so + 2 * TSZ * 2, Bh + boff0[half]);
        cp_async16(so + 3 * TSZ * 2, Bl + boff0[half]);
    }
    CP_COMMIT();

    for (int c = 0; c < nchunk; c++) {
        if (c + 1 < nchunk) {
            int kb = (c + 1) * KC;
            uint32_t stb = sbase + (uint32_t)(((c + 1) & 1) * STG) * 2;
#pragma unroll
            for (int half = 0; half < 2; half++) {
                uint32_t so = stb + (uint32_t)(s_row[half] * LDT + s_c8[half]) * 2;
                cp_async16(so + 0 * TSZ * 2, Ah + aoff0[half] + kb);
                cp_async16(so + 1 * TSZ * 2, Al + aoff0[half] + kb);
                cp_async16(so + 2 * TSZ * 2, Bh + boff0[half] + kb);
                cp_async16(so + 3 * TSZ * 2, Bl + boff0[half] + kb);
            }
            CP_COMMIT();
            CP_WAIT1();
        } else {
            CP_WAIT0();
        }
        __syncthreads();

        const __nv_bfloat16* sAh = smp + (c & 1) * STG;
        const __nv_bfloat16* sAl = sAh + TSZ;
        const __nv_bfloat16* sBh = sAh + 2 * TSZ;
        const __nv_bfloat16* sBl = sAh + 3 * TSZ;

#pragma unroll
        for (int ks = 0; ks < 2; ks++) {
            const int kk = ks * 16 + tig * 2;
            uint32_t ah[2][4], al[2][4];
#pragma unroll
            for (int mt = 0; mt < 2; mt++) {
                int r0 = (wm + mt * 16 + g) * LDT;
                int r1 = r0 + 8 * LDT;
                ah[mt][0] = *(const uint32_t*)&sAh[r0 + kk];
                ah[mt][1] = *(const uint32_t*)&sAh[r1 + kk];
                ah[mt][2] = *(const uint32_t*)&sAh[r0 + kk + 8];
                ah[mt][3] = *(const uint32_t*)&sAh[r1 + kk + 8];
                al[mt][0] = *(const uint32_t*)&sAl[r0 + kk];
                al[mt][1] = *(const uint32_t*)&sAl[r1 + kk];
                al[mt][2] = *(const uint32_t*)&sAl[r0 + kk + 8];
                al[mt][3] = *(const uint32_t*)&sAl[r1 + kk + 8];
            }
#pragma unroll
            for (int nt = 0; nt < 8; nt++) {
                int nrow = (wn + nt * 8 + g) * LDT;
                uint32_t bh0 = *(const uint32_t*)&sBh[nrow + kk];
                uint32_t bh1 = *(const uint32_t*)&sBh[nrow + kk + 8];
                uint32_t bl0 = *(const uint32_t*)&sBl[nrow + kk];
                uint32_t bl1 = *(const uint32_t*)&sBl[nrow + kk + 8];
#pragma unroll
                for (int mt = 0; mt < 2; mt++) {
                    mma16816(acc[mt][nt], ah[mt][0], ah[mt][1], ah[mt][2], ah[mt][3], bh0, bh1);
                    mma16816(acc[mt][nt], ah[mt][0], ah[mt][1], ah[mt][2], ah[mt][3], bl0, bl1);
                    mma16816(acc[mt][nt], al[mt][0], al[mt][1], al[mt][2], al[mt][3], bh0, bh1);
                }
            }
        }
        __syncthreads();
    }

    // ---- epilogue ----
#pragma unroll
    for (int mt = 0; mt < 2; mt++) {
        int row0 = bm + wm + mt * 16 + g;
        int row1 = row0 + 8;
#pragma unroll
        for (int nt = 0; nt < 8; nt++) {
            int col = bn + wn + nt * 8 + tig * 2;
#pragma unroll
            for (int half = 0; half < 2; half++) {
                int row = half ? row1 : row0;
                if (row >= M) continue;
                float v0 = acc[mt][nt][half * 2 + 0];
                float v1 = acc[mt][nt][half * 2 + 1];
                if (mode == 0) {
                    size_t idx = (size_t)row * Nc + col;
                    Cf[idx] = v0; Cf[idx + 1] = v1;
                } else if (mode == 3) {
                    int blk = col >> 8, c2 = col & 255;
                    float* dstp = (blk == 0) ? Cf : ((blk == 1) ? Cf2 : Cf3);
                    size_t idx = (size_t)row * 256 + c2;
                    dstp[idx] = v0; dstp[idx + 1] = v1;
                } else if (mode == 1) {
                    size_t idx = (size_t)row * Nc + col;
                    v0 = fmaxf(v0 + bias[col], 0.f);
                    v1 = fmaxf(v1 + bias[col + 1], 0.f);
                    __nv_bfloat16 h0 = __float2bfloat16(v0);
                    __nv_bfloat16 h1 = __float2bfloat16(v1);
                    Ch[idx] = h0; Ch[idx + 1] = h1;
                    Cl[idx] = __float2bfloat16(v0 - __bfloat162float(h0));
                    Cl[idx + 1] = __float2bfloat16(v1 - __bfloat162float(h1));
                } else {
                    size_t idx = (size_t)row * Nc + col;
                    Cf[idx] = v0 + bias[col] + resid[idx];
                    Cf[idx + 1] = v1 + bias[col + 1] + resid[idx + 1];
                }
            }
        }
    }
}

// ======================= edge attention + softmax (warp per dst node) =======================
__global__ void __launch_bounds__(256) attn_kernel(const float* __restrict__ attnv) {
    __shared__ float sh_e[8][MAXD][8];
    int w = threadIdx.x >> 5;
    int lane = threadIdx.x & 31;
    int v = blockIdx.x * 8 + w;
    if (v >= N_NODES) return;

    float ftl_v[8], at[8];
#pragma unroll
    for (int h = 0; h < 8; h++) {
        ftl_v[h] = g_ftl[(size_t)v * F_DIM + h * 32 + lane];
        at[h] = attnv[h * 32 + lane];
    }
    float ld = g_logdeg[v];
    int s0 = g_rowptr[v], s1 = g_rowptr[v + 1];
    int cnt = s1 - s0;
    int cc = cnt < MAXD ? cnt : MAXD;

    float m8[8];
#pragma unroll
    for (int h = 0; h < 8; h++) m8[h] = -1e30f;

    for (int q = 0; q < cc; q++) {
        int p = s0 + q;
        int s = g_csr_src[p], rr = g_csr_rid[p];
        const float* fhp = &g_fh[(size_t)s * F_DIM + lane];
        const float* frp = &g_fr[(size_t)rr * F_DIM + lane];
#pragma unroll
        for (int h = 0; h < 8; h++) {
            float x = __ldg(fhp + h * 32) * ftl_v[h] * __ldg(frp + h * 32);
            x = x > 0.f ? x : SLOPE * x;
            float e = x * at[h];
#pragma unroll
            for (int o = 16; o; o >>= 1) e += __shfl_xor_sync(0xFFFFFFFFu, e, o);
            e *= ld;
            m8[h] = fmaxf(m8[h], e);
            if (lane == h) sh_e[w][q][h] = e;
        }
    }
    __syncwarp();

    float s8[8];
#pragma unroll
    for (int h = 0; h < 8; h++) s8[h] = 0.f;
    for (int q = lane; q < cc; q += 32) {
#pragma unroll
        for (int h = 0; h < 8; h++) {
            float ex = expf(sh_e[w][q][h] - m8[h]);
            sh_e[w][q][h] = ex;
            s8[h] += ex;
        }
    }
#pragma unroll
    for (int h = 0; h < 8; h++) {
        float t = s8[h];
#pragma unroll
        for (int o = 16; o; o >>= 1) t += __shfl_xor_sync(0xFFFFFFFFu, t, o);
        s8[h] = 1.0f / t;
    }
    __syncwarp();
    for (int q = lane; q < cc; q += 32) {
        int p = s0 + q;
        float4 o0, o1;
        o0.x = sh_e[w][q][0] * s8[0]; o0.y = sh_e[w][q][1] * s8[1];
        o0.z = sh_e[w][q][2] * s8[2]; o0.w = sh_e[w][q][3] * s8[3];
        o1.x = sh_e[w][q][4] * s8[4]; o1.y = sh_e[w][q][5] * s8[5];
        o1.z = sh_e[w][q][6] * s8[6]; o1.w = sh_e[w][q][7] * s8[7];
        *(float4*)&g_a[(size_t)p * 8] = o0;
        *(float4*)&g_a[(size_t)p * 8 + 4] = o1;
    }
}

// ======================= PPR hop (warp per dst node; atomic-free via CSR) =======================
__global__ void __launch_bounds__(256) hop_kernel(const float* __restrict__ fin,
                                                  float* __restrict__ fout) {
    int w = threadIdx.x >> 5, lane = threadIdx.x & 31;
    int v = blockIdx.x * 8 + w;
    if (v >= N_NODES) return;
    int s0 = g_rowptr[v], s1 = g_rowptr[v + 1];
    float acc[8] = {0.f, 0.f, 0.f, 0.f, 0.f, 0.f, 0.f, 0.f};
    for (int p = s0; p < s1; p++) {
        int s = g_csr_src[p];
        const float4* ap = (const float4*)&g_a[(size_t)p * 8];
        float4 a0 = __ldg(ap), a1 = __ldg(ap + 1);
        const float* f = fin + (size_t)s * F_DIM + lane;
        acc[0] += __ldg(f)       * a0.x; acc[1] += __ldg(f + 32)  * a0.y;
        acc[2] += __ldg(f + 64)  * a0.z; acc[3] += __ldg(f + 96)  * a0.w;
        acc[4] += __ldg(f + 128) * a1.x; acc[5] += __ldg(f + 160) * a1.y;
        acc[6] += __ldg(f + 192) * a1.z; acc[7] += __ldg(f + 224) * a1.w;
    }
    size_t base = (size_t)v * F_DIM + lane;
#pragma unroll
    for (int h = 0; h < 8; h++)
        fout[base + h * 32] = 0.9f * acc[h] + 0.1f * g_fen[base + h * 32];
}

// ======================= last hop fused with +ent residual and LN_ff -> yh/yl + rst =======================
__global__ void __launch_bounds__(256) hop_ln_kernel(
    const float* __restrict__ fin, const float* __restrict__ ent,
    const float* __restrict__ gg, const float* __restrict__ bb,
    float* __restrict__ rst, __nv_bfloat16* __restrict__ oh, __nv_bfloat16* __restrict__ ol) {
    int w = threadIdx.x >> 5, lane = threadIdx.x & 31;
    int v = blockIdx.x * 8 + w;
    if (v >= N_NODES) return;
    int s0 = g_rowptr[v], s1 = g_rowptr[v + 1];
    float acc[8] = {0.f, 0.f, 0.f, 0.f, 0.f, 0.f, 0.f, 0.f};
    for (int p = s0; p < s1; p++) {
        int s = g_csr_src[p];
        const float4* ap = (const float4*)&g_a[(size_t)p * 8];
        float4 a0 = __ldg(ap), a1 = __ldg(ap + 1);
        const float* f = fin + (size_t)s * F_DIM + lane;
        acc[0] += __ldg(f)       * a0.x; acc[1] += __ldg(f + 32)  * a0.y;
        acc[2] += __ldg(f + 64)  * a0.z; acc[3] += __ldg(f + 96)  * a0.w;
        acc[4] += __ldg(f + 128) * a1.x; acc[5] += __ldg(f + 160) * a1.y;
        acc[6] += __ldg(f + 192) * a1.z; acc[7] += __ldg(f + 224) * a1.w;
    }
    size_t base = (size_t)v * F_DIM + lane;
    float r[8];
    float s = 0.f, s2 = 0.f;
#pragma unroll
    for (int h = 0; h < 8; h++) {
        r[h] = 0.9f * acc[h] + 0.1f * g_fen[base + h * 32] + ent[base + h * 32];
        rst[base + h * 32] = r[h];
        s += r[h]; s2 += r[h] * r[h];
    }
#pragma unroll
    for (int o = 16; o; o >>= 1) {
        s  += __shfl_xor_sync(0xFFFFFFFFu, s, o);
        s2 += __shfl_xor_sync(0xFFFFFFFFu, s2, o);
    }
    float mean = s * (1.0f / F_DIM);
    float var = s2 * (1.0f / F_DIM) - mean * mean;
    float inv = rsqrtf(var + 1e-5f);
#pragma unroll
    for (int h = 0; h < 8; h++) {
        float y = (r[h] - mean) * inv * gg[h * 32 + lane] + bb[h * 32 + lane];
        __nv_bfloat16 hh = __float2bfloat16(y);
        oh[base + h * 32] = hh;
        ol[base + h * 32] = __float2bfloat16(y - __bfloat162float(hh));
    }
}

// ======================= launch =======================
extern "C" void kernel_launch(void* const* d_in, const int* in_sizes, int n_in,
                              void* d_out, int out_size) {
    const float* ent    = (const float*)d_in[0];
    const float* rel    = (const float*)d_in[1];
    const float* W_head = (const float*)d_in[2];
    const float* W_tail = (const float*)d_in[3];
    const float* W_ent  = (const float*)d_in[4];
    const float* W_rel  = (const float*)d_in[5];
    const float* attnv  = (const float*)d_in[6];
    const float* lne_g = (const float*)d_in[7];
    const float* lne_b = (const float*)d_in[8];
    const float* lnr_g = (const float*)d_in[9];
    const float* lnr_b = (const float*)d_in[10];
    const float* lnf_g = (const float*)d_in[11];
    const float* lnf_b = (const float*)d_in[12];
    const float* W1 = (const float*)d_in[13];
    const float* b1 = (const float*)d_in[14];
    const float* W2 = (const float*)d_in[15];
    const float* b2 = (const float*)d_in[16];
    const int* src = (const int*)d_in[17];
    const int* dst = (const int*)d_in[18];
    const int* rid = (const int*)d_in[19];
    float* out = (float*)d_out;

    float *pfh, *pftl, *pfen, *pfr, *pfeat, *pfeat2, *prst;
    cudaGetSymbolAddress((void**)&pfh, g_fh);
    cudaGetSymbolAddress((void**)&pftl, g_ftl);
    cudaGetSymbolAddress((void**)&pfen, g_fen);
    cudaGetSymbolAddress((void**)&pfr, g_fr);
    cudaGetSymbolAddress((void**)&pfeat, g_feat);
    cudaGetSymbolAddress((void**)&pfeat2, g_feat2);
    cudaGetSymbolAddress((void**)&prst, g_rst);

    int *pdeg, *pcursor;
    cudaGetSymbolAddress((void**)&pdeg, g_deg);
    cudaGetSymbolAddress((void**)&pcursor, g_cursor);

    __nv_bfloat16 *pxh, *pxl, *prh, *prl, *pyh, *pyl, *phh, *phl;
    cudaGetSymbolAddress((void**)&pxh, g_xh);
    cudaGetSymbolAddress((void**)&pxl, g_xl);
    cudaGetSymbolAddress((void**)&prh, g_rh);
    cudaGetSymbolAddress((void**)&prl, g_rl);
    cudaGetSymbolAddress((void**)&pyh, g_yh);
    cudaGetSymbolAddress((void**)&pyl, g_yl);
    cudaGetSymbolAddress((void**)&phh, g_hidh);
    cudaGetSymbolAddress((void**)&phl, g_hidl);

    __nv_bfloat16 *pWph, *pWpl, *pWrh, *pWrl, *pW1h, *pW1l, *pW2h, *pW2l;
    cudaGetSymbolAddress((void**)&pWph, g_Wph); cudaGetSymbolAddress((void**)&pWpl, g_Wpl);
    cudaGetSymbolAddress((void**)&pWrh, g_Wrh); cudaGetSymbolAddress((void**)&pWrl, g_Wrl);
    cudaGetSymbolAddress((void**)&pW1h, g_W1h); cudaGetSymbolAddress((void**)&pW1l, g_W1l);
    cudaGetSymbolAddress((void**)&pW2h, g_W2h); cudaGetSymbolAddress((void**)&pW2l, g_W2l);

    cudaFuncSetAttribute(gemm_mma_kernel, cudaFuncAttributeMaxDynamicSharedMemorySize, GEMM_SMEM);

    // streams/events for overlap (created once; no device allocations)
    static cudaStream_t s1 = nullptr, s2 = nullptr, s3 = nullptr;
    static cudaEvent_t e_fork = nullptr, e_j1 = nullptr, e_j2 = nullptr,
                       e_w = nullptr, e_g1 = nullptr, e_j3 = nullptr;
    if (s1 == nullptr) {
        cudaStreamCreateWithFlags(&s1, cudaStreamNonBlocking);
        cudaStreamCreateWithFlags(&s2, cudaStreamNonBlocking);
        cudaStreamCreateWithFlags(&s3, cudaStreamNonBlocking);
        cudaEventCreateWithFlags(&e_fork, cudaEventDisableTiming);
        cudaEventCreateWithFlags(&e_j1, cudaEventDisableTiming);
        cudaEventCreateWithFlags(&e_j2, cudaEventDisableTiming);
        cudaEventCreateWithFlags(&e_w, cudaEventDisableTiming);
        cudaEventCreateWithFlags(&e_g1, cudaEventDisableTiming);
        cudaEventCreateWithFlags(&e_j3, cudaEventDisableTiming);
    }

    // fork side streams off the capture (legacy) stream
    cudaEventRecord(e_fork, 0);
    cudaStreamWaitEvent(s1, e_fork, 0);
    cudaStreamWaitEvent(s2, e_fork, 0);
    cudaStreamWaitEvent(s3, e_fork, 0);

    // ---- s1: CSR build ----
    cudaMemsetAsync(pdeg, 0, N_NODES * sizeof(int), s1);
    cudaMemsetAsync(pcursor, 0, N_NODES * sizeof(int), s1);
    count_kernel<<<(N_EDGES + 255) / 256, 256, 0, s1>>>(dst);
    scan_kernel<<<1, 1024, 0, s1>>>();
    scatter_kernel<<<(N_EDGES + 255) / 256, 256, 0, s1>>>(src, dst, rid);
    cudaEventRecord(e_j1, s1);

    // ---- s2: proj weight transposes first (needed by G1), then rel path + FFN transposes ----
    dim3 tb(32, 8);
    trans_split_kernel<<<dim3(F_DIM / 32, F_DIM / 32), tb, 0, s2>>>(W_head, F_DIM, F_DIM,
                                                                    pWph + 0 * F_DIM * F_DIM,
                                                                    pWpl + 0 * F_DIM * F_DIM);
    trans_split_kernel<<<dim3(F_DIM / 32, F_DIM / 32), tb, 0, s2>>>(W_tail, F_DIM, F_DIM,
                                                                    pWph + 1 * F_DIM * F_DIM,
                                                                    pWpl + 1 * F_DIM * F_DIM);
    trans_split_kernel<<<dim3(F_DIM / 32, F_DIM / 32), tb, 0, s2>>>(W_ent,  F_DIM, F_DIM,
                                                                    pWph + 2 * F_DIM * F_DIM,
                                                                    pWpl + 2 * F_DIM * F_DIM);
    cudaEventRecord(e_w, s2);
    ln_split_kernel<<<(N_REL + 7) / 8, 256, 0, s2>>>(rel, lnr_g, lnr_b, prh, prl, N_REL);
    trans_split_kernel<<<dim3(F_DIM / 32, F_DIM / 32), tb, 0, s2>>>(W_rel, F_DIM, F_DIM, pWrh, pWrl);
    gemm_mma_kernel<<<dim3(F_DIM / 128, 1), 256, GEMM_SMEM, s2>>>(
        prh, prl, pWrh, pWrl, N_REL, F_DIM, F_DIM,
        pfr, nullptr, nullptr, nullptr, nullptr, nullptr, nullptr, 0);
    trans_split_kernel<<<dim3(FF_DIM / 32, F_DIM / 32), tb, 0, s2>>>(W1, F_DIM, FF_DIM, pW1h, pW1l);
    trans_split_kernel<<<dim3(F_DIM / 32, FF_DIM / 32), tb, 0, s2>>>(W2, FF_DIM, F_DIM, pW2h, pW2l);
    cudaEventRecord(e_j2, s2);

    // ---- main stream: ent LN, then G1 = [fh|ftl] ----
    ln_split_kernel<<<(N_NODES + 7) / 8, 256>>>(ent, lne_g, lne_b, pxh, pxl, N_NODES);
    cudaStreamWaitEvent(0, e_w, 0);
    int mby = (N_NODES + 127) / 128;
    gemm_mma_kernel<<<dim3(512 / 128, mby), 256, GEMM_SMEM>>>(
        pxh, pxl, pWph, pWpl, N_NODES, 512, F_DIM,
        pfh, pftl, nullptr, nullptr, nullptr, nullptr, nullptr, 3);
    cudaEventRecord(e_g1, 0);

    // ---- s3: G2 = fen, concurrent with attention ----
    cudaStreamWaitEvent(s3, e_g1, 0);
    gemm_mma_kernel<<<dim3(F_DIM / 128, mby), 256, GEMM_SMEM, s3>>>(
        pxh, pxl, pWph + 2 * F_DIM * F_DIM, pWpl + 2 * F_DIM * F_DIM, N_NODES, F_DIM, F_DIM,
        pfen, nullptr, nullptr, nullptr, nullptr, nullptr, nullptr, 0);
    cudaEventRecord(e_j3, s3);

    // ---- main: attention (needs G1 + CSR + rel GEMM) ----
    cudaStreamWaitEvent(0, e_j1, 0);
    cudaStreamWaitEvent(0, e_j2, 0);
    attn_kernel<<<(N_NODES + 7) / 8, 256>>>(attnv);

    // ---- hops (hop0 needs fen from G2) ----
    cudaStreamWaitEvent(0, e_j3, 0);
    int nb = (N_NODES + 7) / 8;
    hop_kernel<<<nb, 256>>>(pfen, pfeat);
    hop_kernel<<<nb, 256>>>(pfeat, pfeat2);
    hop_kernel<<<nb, 256>>>(pfeat2, pfeat);
    hop_kernel<<<nb, 256>>>(pfeat, pfeat2);
    hop_ln_kernel<<<nb, 256>>>(pfeat2, ent, lnf_g, lnf_b, prst, pyh, pyl);

    // ---- FFN ----
    gemm_mma_kernel<<<dim3(FF_DIM / 128, mby), 256, GEMM_SMEM>>>(
        pyh, pyl, pW1h, pW1l, N_NODES, FF_DIM, F_DIM,
        nullptr, nullptr, nullptr, phh, phl, b1, nullptr, 1);
    gemm_mma_kernel<<<dim3(F_DIM / 128, mby), 256, GEMM_SMEM>>>(
        phh, phl, pW2h, pW2l, N_NODES, F_DIM, FF_DIM,
        out, nullptr, nullptr, nullptr, nullptr, b2, prst, 2);
}